// round 2
// baseline (speedup 1.0000x reference)
#include <cuda_runtime.h>
#include <cuda_bf16.h>
#include <cstdint>

#define Bsz  8
#define Tlen 1024
#define Hd   1024
#define NG   6144   // fused fwd+rev gate width: [f|o|z]fwd [f|o|z]rev

// ---------------- device scratch (no allocation allowed) -------------------
__device__ float          g_gates[(size_t)Bsz * Tlen * NG];        // 201 MB
__device__ __nv_bfloat16  g_xhi [(size_t)Bsz * Tlen * 1024];
__device__ __nv_bfloat16  g_xlo [(size_t)Bsz * Tlen * 1024];
__device__ __nv_bfloat16  g_o0hi[(size_t)Bsz * Tlen * 2048];
__device__ __nv_bfloat16  g_o0lo[(size_t)Bsz * Tlen * 2048];
__device__ uint32_t       g_wbhi[(size_t)3072 * NG];               // k-pair packed
__device__ uint32_t       g_wblo[(size_t)3072 * NG];

// ---------------------------------------------------------------------------
__device__ __forceinline__ void split2(float a, float b, uint32_t& hp, uint32_t& lp)
{
    __nv_bfloat16 ha = __float2bfloat16(a), hb = __float2bfloat16(b);
    float la = a - __bfloat162float(ha);
    float lb = b - __bfloat162float(hb);
    __nv_bfloat162 hv; hv.x = ha; hv.y = hb;
    __nv_bfloat162 lv; lv.x = __float2bfloat16(la); lv.y = __float2bfloat16(lb);
    hp = *(uint32_t*)&hv; lp = *(uint32_t*)&lv;
}

// split x (fp32) into hi/lo bf16 planes, 4 elems/thread
__global__ void prep_x(const float4* __restrict__ x,
                       uint32_t* __restrict__ hi, uint32_t* __restrict__ lo)
{
    int i = blockIdx.x * blockDim.x + threadIdx.x;   // over float4s
    float4 v = x[i];
    uint32_t h0, l0, h1, l1;
    split2(v.x, v.y, h0, l0);
    split2(v.z, v.w, h1, l1);
    ((uint2*)hi)[i] = make_uint2(h0, h1);
    ((uint2*)lo)[i] = make_uint2(l0, l1);
}

// ---------------------------------------------------------------------------
// weight prep: w [3072, C, 3] fp32  ->  WBhi/WBlo u32 [3C/2][6144]
// reduction index r = tap*C + c; row kp = r/2 packs (r, r+1) bf16 pair
// entry(kp, colbase + j) for output gate j of this direction.
// ---------------------------------------------------------------------------
__global__ void prep_w(const float* __restrict__ w,
                       uint32_t* __restrict__ wbhi, uint32_t* __restrict__ wblo,
                       int C, int colbase)
{
    __shared__ float sm[32][97];
    const int tid = threadIdx.x;
    const int cb = blockIdx.x;   // c-block of 32 channels (96 floats)
    const int jb = blockIdx.y;   // j-block of 32 gates

    for (int i = tid; i < 32 * 96; i += 256) {
        int j = i / 96, q = i % 96;
        sm[j][q] = w[(size_t)(jb * 32 + j) * 3 * C + cb * 96 + q];
    }
    __syncthreads();

    for (int i = tid; i < 1536; i += 256) {
        int tap = i >> 9;            // 0..2
        int kp  = (i >> 5) & 15;     // 0..15
        int j   = i & 31;
        float x0 = sm[j][(kp * 2) * 3 + tap];
        float x1 = sm[j][(kp * 2 + 1) * 3 + tap];
        uint32_t hp, lp;
        split2(x0, x1, hp, lp);
        size_t row = (size_t)tap * (C / 2) + cb * 16 + kp;
        size_t off = row * NG + colbase + jb * 32 + j;
        wbhi[off] = hp; wblo[off] = lp;
    }
}

// ---------------------------------------------------------------------------
__device__ __forceinline__ void cp_async16(uint32_t smem, const void* gmem, int bytes)
{
    asm volatile("cp.async.cg.shared.global [%0], [%1], 16, %2;\n"
                 :: "r"(smem), "l"(gmem), "r"(bytes));
}
__device__ __forceinline__ void cp_commit_wait()
{
    asm volatile("cp.async.commit_group;\n"
                 "cp.async.wait_group 0;\n" ::: "memory");
}

#define MMA_BF16(acc, a, b0, b1)                                              \
    asm volatile("mma.sync.aligned.m16n8k16.row.col.f32.bf16.bf16.f32 "       \
                 "{%0,%1,%2,%3}, {%4,%5,%6,%7}, {%8,%9}, {%0,%1,%2,%3};\n"    \
                 : "+f"(acc[0]), "+f"(acc[1]), "+f"(acc[2]), "+f"(acc[3])     \
                 : "r"(a[0]), "r"(a[1]), "r"(a[2]), "r"(a[3]),                \
                   "r"(b0), "r"(b1));

// ---------------------------------------------------------------------------
// bf16x3 emulated-fp32 conv(K=3)-as-GEMM + bias + activation.
// gates[b*T+t, j] = act( bias + sum_{tap,c} in[b,t+tap-1,c] * w[j,c,tap] )
// A: hi/lo bf16 planes [B*T, C]; B: WBhi/WBlo u32 k-pair planes [3C/2, 6144]
// BM=128 BN=128 BK=32, 256 threads, warp tile 32x64 (4x2 warps)
// ---------------------------------------------------------------------------
template <int C>
__global__ void __launch_bounds__(256, 2) conv_gemm(
    const __nv_bfloat16* __restrict__ Ahi,
    const __nv_bfloat16* __restrict__ Alo,
    const uint32_t* __restrict__ Bhi_,
    const uint32_t* __restrict__ Blo_,
    const float* __restrict__ biasF,
    const float* __restrict__ biasR,
    float* __restrict__ gates)
{
    __shared__ __nv_bfloat16 Ash[128][40];
    __shared__ __nv_bfloat16 Asl[128][40];
    __shared__ uint32_t      Bsh[16][136];
    __shared__ uint32_t      Bsl[16][136];

    const int tid  = threadIdx.x;
    const int lane = tid & 31;
    const int warp = tid >> 5;
    const int wm   = warp & 3;
    const int wn   = warp >> 2;
    const int gp   = lane >> 2;
    const int tg   = lane & 3;

    const int row0 = blockIdx.y << 7;
    const int col0 = blockIdx.x << 7;
    const int t0   = row0 & (Tlen - 1);
    const __nv_bfloat16* Ahb = Ahi + (size_t)(row0 - t0) * C;
    const __nv_bfloat16* Alb = Alo + (size_t)(row0 - t0) * C;

    float acc[2][8][4];
#pragma unroll
    for (int a = 0; a < 2; a++)
#pragma unroll
        for (int b = 0; b < 8; b++)
#pragma unroll
            for (int c = 0; c < 4; c++) acc[a][b][c] = 0.f;

    const int a_m = tid >> 1;            // 0..127
    const int a_c = (tid & 1) << 4;      // 0 / 16 (bf16 elems)
    const int b_r = tid >> 4;            // 0..15
    const int b_c = (tid & 15) << 3;     // 0..120 (u32)

    const uint32_t sAh = (uint32_t)__cvta_generic_to_shared(&Ash[0][0]);
    const uint32_t sAl = (uint32_t)__cvta_generic_to_shared(&Asl[0][0]);
    const uint32_t sBh = (uint32_t)__cvta_generic_to_shared(&Bsh[0][0]);
    const uint32_t sBl = (uint32_t)__cvta_generic_to_shared(&Bsl[0][0]);

    const int NKt = 3 * C / 32;
    for (int kt = 0; kt < NKt; ++kt) {
        const int kbase = kt << 5;
        const int tap   = kbase / C;
        const int cbase = kbase - tap * C;

        __syncthreads();
        // ---- A tile (hi+lo) ----
        {
            int st = t0 + a_m + tap - 1;
            int ok = (st >= 0) && (st < Tlen);
            int stc = ok ? st : 0;
            const __nv_bfloat16* srcH = Ahb + (size_t)stc * C + cbase + a_c;
            const __nv_bfloat16* srcL = Alb + (size_t)stc * C + cbase + a_c;
            uint32_t dA = (uint32_t)(a_m * 40 + a_c) * 2;
            cp_async16(sAh + dA,      srcH,     ok ? 16 : 0);
            cp_async16(sAh + dA + 16, srcH + 8, ok ? 16 : 0);
            cp_async16(sAl + dA,      srcL,     ok ? 16 : 0);
            cp_async16(sAl + dA + 16, srcL + 8, ok ? 16 : 0);
        }
        // ---- B tile (hi+lo) ----
        {
            size_t srcOff = (size_t)(kbase / 2 + b_r) * NG + col0 + b_c;
            uint32_t dB = (uint32_t)(b_r * 136 + b_c) * 4;
            cp_async16(sBh + dB,      Bhi_ + srcOff,     16);
            cp_async16(sBh + dB + 16, Bhi_ + srcOff + 4, 16);
            cp_async16(sBl + dB,      Blo_ + srcOff,     16);
            cp_async16(sBl + dB + 16, Blo_ + srcOff + 4, 16);
        }
        cp_commit_wait();
        __syncthreads();

#pragma unroll
        for (int s = 0; s < 2; s++) {                 // two k16 steps per BK=32
            uint32_t ah[2][4], al[2][4];
#pragma unroll
            for (int mi = 0; mi < 2; mi++) {
                int rm = wm * 32 + mi * 16;
                int k0 = s * 16 + 2 * tg;
                ah[mi][0] = *(const uint32_t*)&Ash[rm + gp    ][k0];
                ah[mi][1] = *(const uint32_t*)&Ash[rm + 8 + gp][k0];
                ah[mi][2] = *(const uint32_t*)&Ash[rm + gp    ][k0 + 8];
                ah[mi][3] = *(const uint32_t*)&Ash[rm + 8 + gp][k0 + 8];
                al[mi][0] = *(const uint32_t*)&Asl[rm + gp    ][k0];
                al[mi][1] = *(const uint32_t*)&Asl[rm + 8 + gp][k0];
                al[mi][2] = *(const uint32_t*)&Asl[rm + gp    ][k0 + 8];
                al[mi][3] = *(const uint32_t*)&Asl[rm + 8 + gp][k0 + 8];
            }
#pragma unroll
            for (int ni = 0; ni < 8; ni++) {
                int col = wn * 64 + ni * 8 + gp;
                uint32_t bh0 = Bsh[s * 8 + tg    ][col];
                uint32_t bh1 = Bsh[s * 8 + tg + 4][col];
                uint32_t bl0 = Bsl[s * 8 + tg    ][col];
                uint32_t bl1 = Bsl[s * 8 + tg + 4][col];
#pragma unroll
                for (int mi = 0; mi < 2; mi++) {
                    MMA_BF16(acc[mi][ni], al[mi], bh0, bh1);   // lo*hi
                    MMA_BF16(acc[mi][ni], ah[mi], bl0, bl1);   // hi*lo
                    MMA_BF16(acc[mi][ni], ah[mi], bh0, bh1);   // hi*hi
                }
            }
        }
    }

    // ---- epilogue: bias + activation ----
    const int  dircol = (col0 >= 3072) ? 1 : 0;
    const float* bias = dircol ? biasR : biasF;
    const int  lcol0  = col0 - dircol * 3072;
    const bool ztan   = (lcol0 >= 2048);   // z section -> tanh, else sigmoid

#pragma unroll
    for (int mi = 0; mi < 2; mi++) {
        int r0g = row0 + wm * 32 + mi * 16 + gp;
#pragma unroll
        for (int ni = 0; ni < 8; ni++) {
            int cl  = lcol0 + wn * 64 + ni * 8 + tg * 2;   // bias index
            int cg  = col0  + wn * 64 + ni * 8 + tg * 2;   // global gate col
            float b0v = bias[cl], b1v = bias[cl + 1];
            float v[4] = { acc[mi][ni][0] + b0v, acc[mi][ni][1] + b1v,
                           acc[mi][ni][2] + b0v, acc[mi][ni][3] + b1v };
#pragma unroll
            for (int j = 0; j < 4; j++) {
                if (ztan) v[j] = 1.f - __fdividef(2.f, __expf(2.f * v[j]) + 1.f);
                else      v[j] = __fdividef(1.f, 1.f + __expf(-v[j]));
            }
            *(float2*)(gates + (size_t)r0g * NG + cg)       = make_float2(v[0], v[1]);
            *(float2*)(gates + (size_t)(r0g + 8) * NG + cg) = make_float2(v[2], v[3]);
        }
    }
}

// ---------------------------------------------------------------------------
// fo-pool scan, both directions via blockIdx.y.
// c_t = f*c_{t-1} + (1-f)*z ;  h_t = c_t * o_t
// L0: write h as hi/lo bf16 planes [B*T, 2048]; L1: write fp32 to d_out.
// hid/cel base already offset by layer; index dir*1024 + b*2048 + h.
// ---------------------------------------------------------------------------
template <bool L0>
__global__ void scan2(const float* __restrict__ gates,
                      float* __restrict__ out_f32,
                      __nv_bfloat16* __restrict__ ohi,
                      __nv_bfloat16* __restrict__ olo,
                      float* __restrict__ hid,
                      float* __restrict__ cel)
{
    const int dir = blockIdx.y;
    const int gid = blockIdx.x * blockDim.x + threadIdx.x;   // 0..8191
    const int b = gid >> 10, h = gid & 1023;
    const float* gb = gates + (size_t)b * Tlen * NG + dir * 3072 + h;
    const size_t obase = (size_t)b * Tlen * 2048 + dir * 1024 + h;
    float c = 0.f;

    auto emit = [&](int t, float hv) {
        size_t idx = obase + (size_t)t * 2048;
        if (L0) {
            __nv_bfloat16 hh = __float2bfloat16(hv);
            ohi[idx] = hh;
            olo[idx] = __float2bfloat16(hv - __bfloat162float(hh));
        } else {
            out_f32[idx] = hv;
        }
    };

    if (dir == 0) {
        float hl = 0.f;
        for (int tt = 0; tt < Tlen; tt += 8) {
            float fv[8], ov[8], zv[8];
#pragma unroll
            for (int i = 0; i < 8; i++) {
                size_t o_ = (size_t)(tt + i) * NG;
                fv[i] = gb[o_]; ov[i] = gb[o_ + 1024]; zv[i] = gb[o_ + 2048];
            }
#pragma unroll
            for (int i = 0; i < 8; i++) {
                c = fmaf(fv[i], c - zv[i], zv[i]);
                hl = c * ov[i];
                emit(tt + i, hl);
            }
        }
        hid[b * 2048 + h] = hl;
        cel[b * 2048 + h] = c;
    } else {
        float cfirst = 0.f, hfirst = 0.f;
        for (int tt = Tlen - 8; tt >= 0; tt -= 8) {
            float fv[8], ov[8], zv[8];
#pragma unroll
            for (int i = 0; i < 8; i++) {
                size_t o_ = (size_t)(tt + i) * NG;
                fv[i] = gb[o_]; ov[i] = gb[o_ + 1024]; zv[i] = gb[o_ + 2048];
            }
#pragma unroll
            for (int i = 7; i >= 0; i--) {
                c = fmaf(fv[i], c - zv[i], zv[i]);
                float hv = c * ov[i];
                emit(tt + i, hv);
                if (tt + i == Tlen - 1) { cfirst = c; hfirst = hv; }
            }
        }
        hid[1024 + b * 2048 + h] = hfirst;
        cel[1024 + b * 2048 + h] = cfirst;
    }
}

// ---------------------------------------------------------------------------
extern "C" void kernel_launch(void* const* d_in, const int* in_sizes, int n_in,
                              void* d_out, int out_size)
{
    const float* x   = (const float*)d_in[0];
    const float* w0f = (const float*)d_in[2];
    const float* b0f = (const float*)d_in[3];
    const float* w0r = (const float*)d_in[4];
    const float* b0r = (const float*)d_in[5];
    const float* w1f = (const float*)d_in[6];
    const float* b1f = (const float*)d_in[7];
    const float* w1r = (const float*)d_in[8];
    const float* b1r = (const float*)d_in[9];

    float* out1 = (float*)d_out;                         // [B,T,2H]
    float* hid  = out1 + (size_t)Bsz * Tlen * 2 * Hd;    // [4,B,H]
    float* cel  = hid + 4 * Bsz * Hd;

    float *gates; __nv_bfloat16 *xhi, *xlo, *o0hi, *o0lo; uint32_t *wbhi, *wblo;
    cudaGetSymbolAddress((void**)&gates, g_gates);
    cudaGetSymbolAddress((void**)&xhi,  g_xhi);
    cudaGetSymbolAddress((void**)&xlo,  g_xlo);
    cudaGetSymbolAddress((void**)&o0hi, g_o0hi);
    cudaGetSymbolAddress((void**)&o0lo, g_o0lo);
    cudaGetSymbolAddress((void**)&wbhi, g_wbhi);
    cudaGetSymbolAddress((void**)&wblo, g_wblo);

    // ---- layer 0 ----
    prep_x<<<8192, 256>>>((const float4*)x, (uint32_t*)xhi, (uint32_t*)xlo);
    prep_w<<<dim3(32, 96), 256>>>(w0f, wbhi, wblo, 1024, 0);
    prep_w<<<dim3(32, 96), 256>>>(w0r, wbhi, wblo, 1024, 3072);
    conv_gemm<1024><<<dim3(48, 64), 256>>>(xhi, xlo, wbhi, wblo, b0f, b0r, gates);
    scan2<true><<<dim3(32, 2), 256>>>(gates, nullptr, o0hi, o0lo, hid, cel);
    // ---- layer 1 ----
    prep_w<<<dim3(64, 96), 256>>>(w1f, wbhi, wblo, 2048, 0);
    prep_w<<<dim3(64, 96), 256>>>(w1r, wbhi, wblo, 2048, 3072);
    conv_gemm<2048><<<dim3(48, 64), 256>>>(o0hi, o0lo, wbhi, wblo, b1f, b1r, gates);
    scan2<false><<<dim3(32, 2), 256>>>(gates, out1, nullptr, nullptr,
                                       hid + 16384, cel + 16384);
}

// round 4
// speedup vs baseline: 1.0115x; 1.0115x over previous
#include <cuda_runtime.h>
#include <cuda_bf16.h>
#include <cstdint>

#define Bsz  8
#define Tlen 1024
#define Hd   1024
#define NG   6144   // fused fwd+rev gate width: [f|o|z]fwd [f|o|z]rev

// ---------------- device scratch (no allocation allowed) -------------------
__device__ float          g_gates[(size_t)Bsz * Tlen * NG];        // 201 MB
__device__ __nv_bfloat16  g_xhi [(size_t)Bsz * Tlen * 1024];
__device__ __nv_bfloat16  g_xlo [(size_t)Bsz * Tlen * 1024];
__device__ __nv_bfloat16  g_o0hi[(size_t)Bsz * Tlen * 2048];
__device__ __nv_bfloat16  g_o0lo[(size_t)Bsz * Tlen * 2048];
__device__ uint32_t       g_wbhi[(size_t)3072 * NG];               // k-pair packed
__device__ uint32_t       g_wblo[(size_t)3072 * NG];

// ---------------------------------------------------------------------------
__device__ __forceinline__ void split2(float a, float b, uint32_t& hp, uint32_t& lp)
{
    __nv_bfloat16 ha = __float2bfloat16(a), hb = __float2bfloat16(b);
    float la = a - __bfloat162float(ha);
    float lb = b - __bfloat162float(hb);
    __nv_bfloat162 hv; hv.x = ha; hv.y = hb;
    __nv_bfloat162 lv; lv.x = __float2bfloat16(la); lv.y = __float2bfloat16(lb);
    hp = *(uint32_t*)&hv; lp = *(uint32_t*)&lv;
}

// split x (fp32) into hi/lo bf16 planes, 4 elems/thread
__global__ void prep_x(const float4* __restrict__ x,
                       uint32_t* __restrict__ hi, uint32_t* __restrict__ lo)
{
    int i = blockIdx.x * blockDim.x + threadIdx.x;   // over float4s
    float4 v = x[i];
    uint32_t h0, l0, h1, l1;
    split2(v.x, v.y, h0, l0);
    split2(v.z, v.w, h1, l1);
    ((uint2*)hi)[i] = make_uint2(h0, h1);
    ((uint2*)lo)[i] = make_uint2(l0, l1);
}

// ---------------------------------------------------------------------------
// weight prep: w [3072, C, 3] fp32  ->  WBhi/WBlo u32 [3C/2][6144]
// reduction index r = tap*C + c; row kp = r/2 packs (r, r+1) bf16 pair
// ---------------------------------------------------------------------------
__global__ void prep_w(const float* __restrict__ w,
                       uint32_t* __restrict__ wbhi, uint32_t* __restrict__ wblo,
                       int C, int colbase)
{
    __shared__ float sm[32][97];
    const int tid = threadIdx.x;
    const int cb = blockIdx.x;   // c-block of 32 channels (96 floats)
    const int jb = blockIdx.y;   // j-block of 32 gates

    for (int i = tid; i < 32 * 96; i += 256) {
        int j = i / 96, q = i % 96;
        sm[j][q] = w[(size_t)(jb * 32 + j) * 3 * C + cb * 96 + q];
    }
    __syncthreads();

    for (int i = tid; i < 1536; i += 256) {
        int tap = i >> 9;            // 0..2
        int kp  = (i >> 5) & 15;     // 0..15
        int j   = i & 31;
        float x0 = sm[j][(kp * 2) * 3 + tap];
        float x1 = sm[j][(kp * 2 + 1) * 3 + tap];
        uint32_t hp, lp;
        split2(x0, x1, hp, lp);
        size_t row = (size_t)tap * (C / 2) + cb * 16 + kp;
        size_t off = row * NG + colbase + jb * 32 + j;
        wbhi[off] = hp; wblo[off] = lp;
    }
}

// ---------------------------------------------------------------------------
__device__ __forceinline__ void cp_async16(uint32_t smem, const void* gmem, int bytes)
{
    asm volatile("cp.async.cg.shared.global [%0], [%1], 16, %2;\n"
                 :: "r"(smem), "l"(gmem), "r"(bytes));
}
__device__ __forceinline__ void cp_commit()
{
    asm volatile("cp.async.commit_group;\n" ::: "memory");
}
template <int N>
__device__ __forceinline__ void cp_wait()
{
    asm volatile("cp.async.wait_group %0;\n" :: "n"(N) : "memory");
}

#define MMA_BF16(acc, a, b0, b1)                                              \
    asm volatile("mma.sync.aligned.m16n8k16.row.col.f32.bf16.bf16.f32 "       \
                 "{%0,%1,%2,%3}, {%4,%5,%6,%7}, {%8,%9}, {%0,%1,%2,%3};\n"    \
                 : "+f"(acc[0]), "+f"(acc[1]), "+f"(acc[2]), "+f"(acc[3])     \
                 : "r"(a[0]), "r"(a[1]), "r"(a[2]), "r"(a[3]),                \
                   "r"(b0), "r"(b1));

// ---------------------------------------------------------------------------
// bf16x3 emulated-fp32 conv(K=3)-as-GEMM + bias + activation.
// Double-buffered cp.async pipeline (2 stages).
// A: hi/lo bf16 planes [B*T, C]; B: WBhi/WBlo u32 k-pair planes [3C/2, 6144]
// BM=128 BN=128 BK=32, 256 threads, warp tile 32x64 (4x2 warps)
// ---------------------------------------------------------------------------
// per-stage smem block layout (bytes):
//   Ash 128*40*2 = 10240 | Asl 10240 | Bsh 16*136*4 = 8704 | Bsl 8704
#define ST_ASL 10240
#define ST_BSH 20480
#define ST_BSL 29184
#define ST_SZ  37888
#define SMEM_TOTAL (2 * ST_SZ)

template <int C>
__global__ void __launch_bounds__(256, 2) conv_gemm(
    const __nv_bfloat16* __restrict__ Ahi,
    const __nv_bfloat16* __restrict__ Alo,
    const uint32_t* __restrict__ Bhi_,
    const uint32_t* __restrict__ Blo_,
    const float* __restrict__ biasF,
    const float* __restrict__ biasR,
    float* __restrict__ gates)
{
    extern __shared__ char smraw[];

    const int tid  = threadIdx.x;
    const int lane = tid & 31;
    const int warp = tid >> 5;
    const int wm   = warp & 3;
    const int wn   = warp >> 2;
    const int gp   = lane >> 2;
    const int tg   = lane & 3;

    const int row0 = blockIdx.y << 7;
    const int col0 = blockIdx.x << 7;
    const int t0   = row0 & (Tlen - 1);
    const __nv_bfloat16* Ahb = Ahi + (size_t)(row0 - t0) * C;
    const __nv_bfloat16* Alb = Alo + (size_t)(row0 - t0) * C;

    float acc[2][8][4];
#pragma unroll
    for (int a = 0; a < 2; a++)
#pragma unroll
        for (int b = 0; b < 8; b++)
#pragma unroll
            for (int c = 0; c < 4; c++) acc[a][b][c] = 0.f;

    const int a_m = tid >> 1;            // 0..127
    const int a_c = (tid & 1) << 4;      // 0 / 16 (bf16 elems)
    const int b_r = tid >> 4;            // 0..15
    const int b_c = (tid & 15) << 3;     // 0..120 (u32)

    uint32_t sbase;
    asm("{ .reg .u64 t; cvta.to.shared.u64 t, %1; cvt.u32.u64 %0, t; }"
        : "=r"(sbase) : "l"(smraw));

    const int NKt = 3 * C / 32;

    // ---- stage loader ----
    auto load_stage = [&](int kt, int s) {
        const int kbase = kt << 5;
        const int tap   = kbase / C;
        const int cbase = kbase - tap * C;
        const uint32_t st = sbase + s * ST_SZ;
        // A tile (hi+lo)
        {
            int stt = t0 + a_m + tap - 1;
            int ok  = (stt >= 0) && (stt < Tlen);
            int stc = ok ? stt : 0;
            const __nv_bfloat16* srcH = Ahb + (size_t)stc * C + cbase + a_c;
            const __nv_bfloat16* srcL = Alb + (size_t)stc * C + cbase + a_c;
            uint32_t dA = st + (uint32_t)(a_m * 40 + a_c) * 2;
            cp_async16(dA,               srcH,     ok ? 16 : 0);
            cp_async16(dA + 16,          srcH + 8, ok ? 16 : 0);
            cp_async16(dA + ST_ASL,      srcL,     ok ? 16 : 0);
            cp_async16(dA + ST_ASL + 16, srcL + 8, ok ? 16 : 0);
        }
        // B tile (hi+lo)
        {
            size_t srcOff = (size_t)(kbase / 2 + b_r) * NG + col0 + b_c;
            uint32_t dB = st + ST_BSH + (uint32_t)(b_r * 136 + b_c) * 4;
            cp_async16(dB,                        Bhi_ + srcOff,     16);
            cp_async16(dB + 16,                   Bhi_ + srcOff + 4, 16);
            cp_async16(dB + (ST_BSL - ST_BSH),      Blo_ + srcOff,     16);
            cp_async16(dB + (ST_BSL - ST_BSH) + 16, Blo_ + srcOff + 4, 16);
        }
    };

    load_stage(0, 0);
    cp_commit();

    for (int kt = 0; kt < NKt; ++kt) {
        const int s = kt & 1;
        if (kt + 1 < NKt) {
            load_stage(kt + 1, s ^ 1);
            cp_commit();
            cp_wait<1>();
        } else {
            cp_wait<0>();
        }
        __syncthreads();

        const char* st = smraw + s * ST_SZ;
        const __nv_bfloat16 (*Ash)[40] = (const __nv_bfloat16 (*)[40])(st);
        const __nv_bfloat16 (*Asl)[40] = (const __nv_bfloat16 (*)[40])(st + ST_ASL);
        const uint32_t (*Bsh)[136] = (const uint32_t (*)[136])(st + ST_BSH);
        const uint32_t (*Bsl)[136] = (const uint32_t (*)[136])(st + ST_BSL);

#pragma unroll
        for (int ks = 0; ks < 2; ks++) {              // two k16 steps per BK=32
            uint32_t ah[2][4], al[2][4];
#pragma unroll
            for (int mi = 0; mi < 2; mi++) {
                int rm = wm * 32 + mi * 16;
                int k0 = ks * 16 + 2 * tg;
                ah[mi][0] = *(const uint32_t*)&Ash[rm + gp    ][k0];
                ah[mi][1] = *(const uint32_t*)&Ash[rm + 8 + gp][k0];
                ah[mi][2] = *(const uint32_t*)&Ash[rm + gp    ][k0 + 8];
                ah[mi][3] = *(const uint32_t*)&Ash[rm + 8 + gp][k0 + 8];
                al[mi][0] = *(const uint32_t*)&Asl[rm + gp    ][k0];
                al[mi][1] = *(const uint32_t*)&Asl[rm + 8 + gp][k0];
                al[mi][2] = *(const uint32_t*)&Asl[rm + gp    ][k0 + 8];
                al[mi][3] = *(const uint32_t*)&Asl[rm + 8 + gp][k0 + 8];
            }
#pragma unroll
            for (int ni = 0; ni < 8; ni++) {
                int col = wn * 64 + ni * 8 + gp;
                uint32_t bh0 = Bsh[ks * 8 + tg    ][col];
                uint32_t bh1 = Bsh[ks * 8 + tg + 4][col];
                uint32_t bl0 = Bsl[ks * 8 + tg    ][col];
                uint32_t bl1 = Bsl[ks * 8 + tg + 4][col];
#pragma unroll
                for (int mi = 0; mi < 2; mi++) {
                    MMA_BF16(acc[mi][ni], al[mi], bh0, bh1);   // lo*hi
                    MMA_BF16(acc[mi][ni], ah[mi], bl0, bl1);   // hi*lo
                    MMA_BF16(acc[mi][ni], ah[mi], bh0, bh1);   // hi*hi
                }
            }
        }
        __syncthreads();
    }

    // ---- epilogue: bias + activation ----
    const int  dircol = (col0 >= 3072) ? 1 : 0;
    const float* bias = dircol ? biasR : biasF;
    const int  lcol0  = col0 - dircol * 3072;
    const bool ztan   = (lcol0 >= 2048);   // z section -> tanh, else sigmoid

#pragma unroll
    for (int mi = 0; mi < 2; mi++) {
        int r0g = row0 + wm * 32 + mi * 16 + gp;
#pragma unroll
        for (int ni = 0; ni < 8; ni++) {
            int cl  = lcol0 + wn * 64 + ni * 8 + tg * 2;   // bias index
            int cg  = col0  + wn * 64 + ni * 8 + tg * 2;   // global gate col
            float b0v = bias[cl], b1v = bias[cl + 1];
            float v[4] = { acc[mi][ni][0] + b0v, acc[mi][ni][1] + b1v,
                           acc[mi][ni][2] + b0v, acc[mi][ni][3] + b1v };
#pragma unroll
            for (int j = 0; j < 4; j++) {
                if (ztan) v[j] = 1.f - __fdividef(2.f, __expf(2.f * v[j]) + 1.f);
                else      v[j] = __fdividef(1.f, 1.f + __expf(-v[j]));
            }
            *(float2*)(gates + (size_t)r0g * NG + cg)       = make_float2(v[0], v[1]);
            *(float2*)(gates + (size_t)(r0g + 8) * NG + cg) = make_float2(v[2], v[3]);
        }
    }
}

// ---------------------------------------------------------------------------
// fo-pool scan, both directions via blockIdx.y.
// c_t = f*c_{t-1} + (1-f)*z ;  h_t = c_t * o_t
// L0: write h as hi/lo bf16 planes [B*T, 2048]; L1: write fp32 to d_out.
// ---------------------------------------------------------------------------
template <bool L0>
__global__ void scan2(const float* __restrict__ gates,
                      float* __restrict__ out_f32,
                      __nv_bfloat16* __restrict__ ohi,
                      __nv_bfloat16* __restrict__ olo,
                      float* __restrict__ hid,
                      float* __restrict__ cel)
{
    const int dir = blockIdx.y;
    const int gid = blockIdx.x * blockDim.x + threadIdx.x;   // 0..8191
    const int b = gid >> 10, h = gid & 1023;
    const float* gb = gates + (size_t)b * Tlen * NG + dir * 3072 + h;
    const size_t obase = (size_t)b * Tlen * 2048 + dir * 1024 + h;
    float c = 0.f;

    auto emit = [&](int t, float hv) {
        size_t idx = obase + (size_t)t * 2048;
        if (L0) {
            __nv_bfloat16 hh = __float2bfloat16(hv);
            ohi[idx] = hh;
            olo[idx] = __float2bfloat16(hv - __bfloat162float(hh));
        } else {
            out_f32[idx] = hv;
        }
    };

    if (dir == 0) {
        float hl = 0.f;
        for (int tt = 0; tt < Tlen; tt += 8) {
            float fv[8], ov[8], zv[8];
#pragma unroll
            for (int i = 0; i < 8; i++) {
                size_t o_ = (size_t)(tt + i) * NG;
                fv[i] = gb[o_]; ov[i] = gb[o_ + 1024]; zv[i] = gb[o_ + 2048];
            }
#pragma unroll
            for (int i = 0; i < 8; i++) {
                c = fmaf(fv[i], c - zv[i], zv[i]);
                hl = c * ov[i];
                emit(tt + i, hl);
            }
        }
        hid[b * 2048 + h] = hl;
        cel[b * 2048 + h] = c;
    } else {
        float cfirst = 0.f, hfirst = 0.f;
        for (int tt = Tlen - 8; tt >= 0; tt -= 8) {
            float fv[8], ov[8], zv[8];
#pragma unroll
            for (int i = 0; i < 8; i++) {
                size_t o_ = (size_t)(tt + i) * NG;
                fv[i] = gb[o_]; ov[i] = gb[o_ + 1024]; zv[i] = gb[o_ + 2048];
            }
#pragma unroll
            for (int i = 7; i >= 0; i--) {
                c = fmaf(fv[i], c - zv[i], zv[i]);
                float hv = c * ov[i];
                emit(tt + i, hv);
                if (tt + i == Tlen - 1) { cfirst = c; hfirst = hv; }
            }
        }
        hid[1024 + b * 2048 + h] = hfirst;
        cel[1024 + b * 2048 + h] = cfirst;
    }
}

// ---------------------------------------------------------------------------
extern "C" void kernel_launch(void* const* d_in, const int* in_sizes, int n_in,
                              void* d_out, int out_size)
{
    const float* x   = (const float*)d_in[0];
    const float* w0f = (const float*)d_in[2];
    const float* b0f = (const float*)d_in[3];
    const float* w0r = (const float*)d_in[4];
    const float* b0r = (const float*)d_in[5];
    const float* w1f = (const float*)d_in[6];
    const float* b1f = (const float*)d_in[7];
    const float* w1r = (const float*)d_in[8];
    const float* b1r = (const float*)d_in[9];

    float* out1 = (float*)d_out;                         // [B,T,2H]
    float* hid  = out1 + (size_t)Bsz * Tlen * 2 * Hd;    // [4,B,H]
    float* cel  = hid + 4 * Bsz * Hd;

    float *gates; __nv_bfloat16 *xhi, *xlo, *o0hi, *o0lo; uint32_t *wbhi, *wblo;
    cudaGetSymbolAddress((void**)&gates, g_gates);
    cudaGetSymbolAddress((void**)&xhi,  g_xhi);
    cudaGetSymbolAddress((void**)&xlo,  g_xlo);
    cudaGetSymbolAddress((void**)&o0hi, g_o0hi);
    cudaGetSymbolAddress((void**)&o0lo, g_o0lo);
    cudaGetSymbolAddress((void**)&wbhi, g_wbhi);
    cudaGetSymbolAddress((void**)&wblo, g_wblo);

    cudaFuncSetAttribute(conv_gemm<1024>,
                         cudaFuncAttributeMaxDynamicSharedMemorySize, SMEM_TOTAL);
    cudaFuncSetAttribute(conv_gemm<2048>,
                         cudaFuncAttributeMaxDynamicSharedMemorySize, SMEM_TOTAL);

    // ---- layer 0 ----
    prep_x<<<8192, 256>>>((const float4*)x, (uint32_t*)xhi, (uint32_t*)xlo);
    prep_w<<<dim3(32, 96), 256>>>(w0f, wbhi, wblo, 1024, 0);
    prep_w<<<dim3(32, 96), 256>>>(w0r, wbhi, wblo, 1024, 3072);
    conv_gemm<1024><<<dim3(48, 64), 256, SMEM_TOTAL>>>(xhi, xlo, wbhi, wblo,
                                                       b0f, b0r, gates);
    scan2<true><<<dim3(32, 2), 256>>>(gates, nullptr, o0hi, o0lo, hid, cel);
    // ---- layer 1 ----
    prep_w<<<dim3(64, 96), 256>>>(w1f, wbhi, wblo, 2048, 0);
    prep_w<<<dim3(64, 96), 256>>>(w1r, wbhi, wblo, 2048, 3072);
    conv_gemm<2048><<<dim3(48, 64), 256, SMEM_TOTAL>>>(o0hi, o0lo, wbhi, wblo,
                                                       b1f, b1r, gates);
    scan2<false><<<dim3(32, 2), 256>>>(gates, out1, nullptr, nullptr,
                                       hid + 16384, cel + 16384);
}

// round 5
// speedup vs baseline: 1.0590x; 1.0470x over previous
#include <cuda_runtime.h>
#include <cuda_bf16.h>
#include <cstdint>

#define Bsz  8
#define Tlen 1024
#define Hd   1024
#define NG   6144   // fused fwd+rev gate width: [f|o|z]fwd [f|o|z]rev

// ---------------- device scratch (no allocation allowed) -------------------
__device__ float          g_gates[(size_t)Bsz * Tlen * NG];        // 201 MB
__device__ __nv_bfloat16  g_xhi [(size_t)Bsz * Tlen * 1024];
__device__ __nv_bfloat16  g_xlo [(size_t)Bsz * Tlen * 1024];
__device__ __nv_bfloat16  g_o0hi[(size_t)Bsz * Tlen * 2048];
__device__ __nv_bfloat16  g_o0lo[(size_t)Bsz * Tlen * 2048];
__device__ uint32_t       g_wbhi[(size_t)3072 * NG];               // k-pair packed
__device__ uint32_t       g_wblo[(size_t)3072 * NG];

// ---------------------------------------------------------------------------
__device__ __forceinline__ void split2(float a, float b, uint32_t& hp, uint32_t& lp)
{
    __nv_bfloat16 ha = __float2bfloat16(a), hb = __float2bfloat16(b);
    float la = a - __bfloat162float(ha);
    float lb = b - __bfloat162float(hb);
    __nv_bfloat162 hv; hv.x = ha; hv.y = hb;
    __nv_bfloat162 lv; lv.x = __float2bfloat16(la); lv.y = __float2bfloat16(lb);
    hp = *(uint32_t*)&hv; lp = *(uint32_t*)&lv;
}

// split x (fp32) into hi/lo bf16 planes, 4 elems/thread
__global__ void prep_x(const float4* __restrict__ x,
                       uint32_t* __restrict__ hi, uint32_t* __restrict__ lo)
{
    int i = blockIdx.x * blockDim.x + threadIdx.x;   // over float4s
    float4 v = x[i];
    uint32_t h0, l0, h1, l1;
    split2(v.x, v.y, h0, l0);
    split2(v.z, v.w, h1, l1);
    ((uint2*)hi)[i] = make_uint2(h0, h1);
    ((uint2*)lo)[i] = make_uint2(l0, l1);
}

// ---------------------------------------------------------------------------
// weight prep: w [3072, C, 3] fp32  ->  WBhi/WBlo u32 [3C/2][6144]
// reduction index r = tap*C + c; row kp = r/2 packs (r, r+1) bf16 pair
// ---------------------------------------------------------------------------
__global__ void prep_w(const float* __restrict__ w,
                       uint32_t* __restrict__ wbhi, uint32_t* __restrict__ wblo,
                       int C, int colbase)
{
    __shared__ float sm[32][97];
    const int tid = threadIdx.x;
    const int cb = blockIdx.x;   // c-block of 32 channels (96 floats)
    const int jb = blockIdx.y;   // j-block of 32 gates

    for (int i = tid; i < 32 * 96; i += 256) {
        int j = i / 96, q = i % 96;
        sm[j][q] = w[(size_t)(jb * 32 + j) * 3 * C + cb * 96 + q];
    }
    __syncthreads();

    for (int i = tid; i < 1536; i += 256) {
        int tap = i >> 9;            // 0..2
        int kp  = (i >> 5) & 15;     // 0..15
        int j   = i & 31;
        float x0 = sm[j][(kp * 2) * 3 + tap];
        float x1 = sm[j][(kp * 2 + 1) * 3 + tap];
        uint32_t hp, lp;
        split2(x0, x1, hp, lp);
        size_t row = (size_t)tap * (C / 2) + cb * 16 + kp;
        size_t off = row * NG + colbase + jb * 32 + j;
        wbhi[off] = hp; wblo[off] = lp;
    }
}

// ---------------------------------------------------------------------------
__device__ __forceinline__ void cp_async16(uint32_t smem, const void* gmem, int bytes)
{
    asm volatile("cp.async.cg.shared.global [%0], [%1], 16, %2;\n"
                 :: "r"(smem), "l"(gmem), "r"(bytes));
}
__device__ __forceinline__ void cp_commit()
{
    asm volatile("cp.async.commit_group;\n" ::: "memory");
}
template <int N>
__device__ __forceinline__ void cp_wait()
{
    asm volatile("cp.async.wait_group %0;\n" :: "n"(N) : "memory");
}

#define MMA_BF16(acc, a, b0, b1)                                              \
    asm volatile("mma.sync.aligned.m16n8k16.row.col.f32.bf16.bf16.f32 "       \
                 "{%0,%1,%2,%3}, {%4,%5,%6,%7}, {%8,%9}, {%0,%1,%2,%3};\n"    \
                 : "+f"(acc[0]), "+f"(acc[1]), "+f"(acc[2]), "+f"(acc[3])     \
                 : "r"(a[0]), "r"(a[1]), "r"(a[2]), "r"(a[3]),                \
                   "r"(b0), "r"(b1));

// ---------------------------------------------------------------------------
// bf16x3 emulated-fp32 conv(K=3)-as-GEMM + bias + activation.
// Double-buffered cp.async pipeline (2 stages); term-outermost MMA ordering
// to break accumulator RAW chains.
// BM=128 BN=128 BK=32, 256 threads, warp tile 32x64 (4x2 warps)
// ---------------------------------------------------------------------------
// per-stage smem block layout (bytes):
//   Ash 128*40*2 = 10240 | Asl 10240 | Bsh 16*136*4 = 8704 | Bsl 8704
#define ST_ASL 10240
#define ST_BSH 20480
#define ST_BSL 29184
#define ST_SZ  37888
#define SMEM_TOTAL (2 * ST_SZ)

template <int C>
__global__ void __launch_bounds__(256, 2) conv_gemm(
    const __nv_bfloat16* __restrict__ Ahi,
    const __nv_bfloat16* __restrict__ Alo,
    const uint32_t* __restrict__ Bhi_,
    const uint32_t* __restrict__ Blo_,
    const float* __restrict__ biasF,
    const float* __restrict__ biasR,
    float* __restrict__ gates)
{
    extern __shared__ char smraw[];

    const int tid  = threadIdx.x;
    const int lane = tid & 31;
    const int warp = tid >> 5;
    const int wm   = warp & 3;
    const int wn   = warp >> 2;
    const int gp   = lane >> 2;
    const int tg   = lane & 3;

    const int row0 = blockIdx.y << 7;
    const int col0 = blockIdx.x << 7;
    const int t0   = row0 & (Tlen - 1);
    const __nv_bfloat16* Ahb = Ahi + (size_t)(row0 - t0) * C;
    const __nv_bfloat16* Alb = Alo + (size_t)(row0 - t0) * C;

    float acc[2][8][4];
#pragma unroll
    for (int a = 0; a < 2; a++)
#pragma unroll
        for (int b = 0; b < 8; b++)
#pragma unroll
            for (int c = 0; c < 4; c++) acc[a][b][c] = 0.f;

    const int a_m = tid >> 1;            // 0..127
    const int a_c = (tid & 1) << 4;      // 0 / 16 (bf16 elems)
    const int b_r = tid >> 4;            // 0..15
    const int b_c = (tid & 15) << 3;     // 0..120 (u32)

    uint32_t sbase;
    asm("{ .reg .u64 t; cvta.to.shared.u64 t, %1; cvt.u32.u64 %0, t; }"
        : "=r"(sbase) : "l"(smraw));

    const int NKt = 3 * C / 32;

    // ---- stage loader ----
    auto load_stage = [&](int kt, int s) {
        const int kbase = kt << 5;
        const int tap   = kbase / C;
        const int cbase = kbase - tap * C;
        const uint32_t st = sbase + s * ST_SZ;
        // A tile (hi+lo)
        {
            int stt = t0 + a_m + tap - 1;
            int ok  = (stt >= 0) && (stt < Tlen);
            int stc = ok ? stt : 0;
            const __nv_bfloat16* srcH = Ahb + (size_t)stc * C + cbase + a_c;
            const __nv_bfloat16* srcL = Alb + (size_t)stc * C + cbase + a_c;
            uint32_t dA = st + (uint32_t)(a_m * 40 + a_c) * 2;
            cp_async16(dA,               srcH,     ok ? 16 : 0);
            cp_async16(dA + 16,          srcH + 8, ok ? 16 : 0);
            cp_async16(dA + ST_ASL,      srcL,     ok ? 16 : 0);
            cp_async16(dA + ST_ASL + 16, srcL + 8, ok ? 16 : 0);
        }
        // B tile (hi+lo)
        {
            size_t srcOff = (size_t)(kbase / 2 + b_r) * NG + col0 + b_c;
            uint32_t dB = st + ST_BSH + (uint32_t)(b_r * 136 + b_c) * 4;
            cp_async16(dB,                          Bhi_ + srcOff,     16);
            cp_async16(dB + 16,                     Bhi_ + srcOff + 4, 16);
            cp_async16(dB + (ST_BSL - ST_BSH),      Blo_ + srcOff,     16);
            cp_async16(dB + (ST_BSL - ST_BSH) + 16, Blo_ + srcOff + 4, 16);
        }
    };

    load_stage(0, 0);
    cp_commit();

    for (int kt = 0; kt < NKt; ++kt) {
        const int s = kt & 1;
        if (kt + 1 < NKt) {
            load_stage(kt + 1, s ^ 1);
            cp_commit();
            cp_wait<1>();
        } else {
            cp_wait<0>();
        }
        __syncthreads();

        const char* st = smraw + s * ST_SZ;
        const __nv_bfloat16 (*Ash)[40] = (const __nv_bfloat16 (*)[40])(st);
        const __nv_bfloat16 (*Asl)[40] = (const __nv_bfloat16 (*)[40])(st + ST_ASL);
        const uint32_t (*Bsh)[136] = (const uint32_t (*)[136])(st + ST_BSH);
        const uint32_t (*Bsl)[136] = (const uint32_t (*)[136])(st + ST_BSL);

#pragma unroll
        for (int ks = 0; ks < 2; ks++) {              // two k16 steps per BK=32
            // ---- preload all A fragments for this k16 step ----
            uint32_t ah[2][4], al[2][4];
#pragma unroll
            for (int mi = 0; mi < 2; mi++) {
                int rm = wm * 32 + mi * 16;
                int k0 = ks * 16 + 2 * tg;
                ah[mi][0] = *(const uint32_t*)&Ash[rm + gp    ][k0];
                ah[mi][1] = *(const uint32_t*)&Ash[rm + 8 + gp][k0];
                ah[mi][2] = *(const uint32_t*)&Ash[rm + gp    ][k0 + 8];
                ah[mi][3] = *(const uint32_t*)&Ash[rm + 8 + gp][k0 + 8];
                al[mi][0] = *(const uint32_t*)&Asl[rm + gp    ][k0];
                al[mi][1] = *(const uint32_t*)&Asl[rm + 8 + gp][k0];
                al[mi][2] = *(const uint32_t*)&Asl[rm + gp    ][k0 + 8];
                al[mi][3] = *(const uint32_t*)&Asl[rm + 8 + gp][k0 + 8];
            }
            // ---- process ni in groups of 4; term-outermost inside group ----
#pragma unroll
            for (int nh = 0; nh < 2; nh++) {
                uint32_t bh[4][2], bl[4][2];
#pragma unroll
                for (int nj = 0; nj < 4; nj++) {
                    int col = wn * 64 + (nh * 4 + nj) * 8 + gp;
                    bh[nj][0] = Bsh[ks * 8 + tg    ][col];
                    bh[nj][1] = Bsh[ks * 8 + tg + 4][col];
                    bl[nj][0] = Bsl[ks * 8 + tg    ][col];
                    bl[nj][1] = Bsl[ks * 8 + tg + 4][col];
                }
                // term 1: lo*hi — 8 independent MMAs
#pragma unroll
                for (int nj = 0; nj < 4; nj++)
#pragma unroll
                    for (int mi = 0; mi < 2; mi++) {
                        MMA_BF16(acc[mi][nh * 4 + nj], al[mi],
                                 bh[nj][0], bh[nj][1]);
                    }
                // term 2: hi*lo
#pragma unroll
                for (int nj = 0; nj < 4; nj++)
#pragma unroll
                    for (int mi = 0; mi < 2; mi++) {
                        MMA_BF16(acc[mi][nh * 4 + nj], ah[mi],
                                 bl[nj][0], bl[nj][1]);
                    }
                // term 3: hi*hi
#pragma unroll
                for (int nj = 0; nj < 4; nj++)
#pragma unroll
                    for (int mi = 0; mi < 2; mi++) {
                        MMA_BF16(acc[mi][nh * 4 + nj], ah[mi],
                                 bh[nj][0], bh[nj][1]);
                    }
            }
        }
        __syncthreads();
    }

    // ---- epilogue: bias + activation ----
    const int  dircol = (col0 >= 3072) ? 1 : 0;
    const float* bias = dircol ? biasR : biasF;
    const int  lcol0  = col0 - dircol * 3072;
    const bool ztan   = (lcol0 >= 2048);   // z section -> tanh, else sigmoid

#pragma unroll
    for (int mi = 0; mi < 2; mi++) {
        int r0g = row0 + wm * 32 + mi * 16 + gp;
#pragma unroll
        for (int ni = 0; ni < 8; ni++) {
            int cl  = lcol0 + wn * 64 + ni * 8 + tg * 2;   // bias index
            int cg  = col0  + wn * 64 + ni * 8 + tg * 2;   // global gate col
            float b0v = bias[cl], b1v = bias[cl + 1];
            float v[4] = { acc[mi][ni][0] + b0v, acc[mi][ni][1] + b1v,
                           acc[mi][ni][2] + b0v, acc[mi][ni][3] + b1v };
#pragma unroll
            for (int j = 0; j < 4; j++) {
                if (ztan) v[j] = 1.f - __fdividef(2.f, __expf(2.f * v[j]) + 1.f);
                else      v[j] = __fdividef(1.f, 1.f + __expf(-v[j]));
            }
            *(float2*)(gates + (size_t)r0g * NG + cg)       = make_float2(v[0], v[1]);
            *(float2*)(gates + (size_t)(r0g + 8) * NG + cg) = make_float2(v[2], v[3]);
        }
    }
}

// ---------------------------------------------------------------------------
// fo-pool scan, both directions via blockIdx.y.
// c_t = f*c_{t-1} + (1-f)*z ;  h_t = c_t * o_t
// L0: write h as hi/lo bf16 planes [B*T, 2048]; L1: write fp32 to d_out.
// ---------------------------------------------------------------------------
template <bool L0>
__global__ void scan2(const float* __restrict__ gates,
                      float* __restrict__ out_f32,
                      __nv_bfloat16* __restrict__ ohi,
                      __nv_bfloat16* __restrict__ olo,
                      float* __restrict__ hid,
                      float* __restrict__ cel)
{
    const int dir = blockIdx.y;
    const int gid = blockIdx.x * blockDim.x + threadIdx.x;   // 0..8191
    const int b = gid >> 10, h = gid & 1023;
    const float* gb = gates + (size_t)b * Tlen * NG + dir * 3072 + h;
    const size_t obase = (size_t)b * Tlen * 2048 + dir * 1024 + h;
    float c = 0.f;

    auto emit = [&](int t, float hv) {
        size_t idx = obase + (size_t)t * 2048;
        if (L0) {
            __nv_bfloat16 hh = __float2bfloat16(hv);
            ohi[idx] = hh;
            olo[idx] = __float2bfloat16(hv - __bfloat162float(hh));
        } else {
            out_f32[idx] = hv;
        }
    };

    if (dir == 0) {
        float hl = 0.f;
        for (int tt = 0; tt < Tlen; tt += 8) {
            float fv[8], ov[8], zv[8];
#pragma unroll
            for (int i = 0; i < 8; i++) {
                size_t o_ = (size_t)(tt + i) * NG;
                fv[i] = gb[o_]; ov[i] = gb[o_ + 1024]; zv[i] = gb[o_ + 2048];
            }
#pragma unroll
            for (int i = 0; i < 8; i++) {
                c = fmaf(fv[i], c - zv[i], zv[i]);
                hl = c * ov[i];
                emit(tt + i, hl);
            }
        }
        hid[b * 2048 + h] = hl;
        cel[b * 2048 + h] = c;
    } else {
        float cfirst = 0.f, hfirst = 0.f;
        for (int tt = Tlen - 8; tt >= 0; tt -= 8) {
            float fv[8], ov[8], zv[8];
#pragma unroll
            for (int i = 0; i < 8; i++) {
                size_t o_ = (size_t)(tt + i) * NG;
                fv[i] = gb[o_]; ov[i] = gb[o_ + 1024]; zv[i] = gb[o_ + 2048];
            }
#pragma unroll
            for (int i = 7; i >= 0; i--) {
                c = fmaf(fv[i], c - zv[i], zv[i]);
                float hv = c * ov[i];
                emit(tt + i, hv);
                if (tt + i == Tlen - 1) { cfirst = c; hfirst = hv; }
            }
        }
        hid[1024 + b * 2048 + h] = hfirst;
        cel[1024 + b * 2048 + h] = cfirst;
    }
}

// ---------------------------------------------------------------------------
extern "C" void kernel_launch(void* const* d_in, const int* in_sizes, int n_in,
                              void* d_out, int out_size)
{
    const float* x   = (const float*)d_in[0];
    const float* w0f = (const float*)d_in[2];
    const float* b0f = (const float*)d_in[3];
    const float* w0r = (const float*)d_in[4];
    const float* b0r = (const float*)d_in[5];
    const float* w1f = (const float*)d_in[6];
    const float* b1f = (const float*)d_in[7];
    const float* w1r = (const float*)d_in[8];
    const float* b1r = (const float*)d_in[9];

    float* out1 = (float*)d_out;                         // [B,T,2H]
    float* hid  = out1 + (size_t)Bsz * Tlen * 2 * Hd;    // [4,B,H]
    float* cel  = hid + 4 * Bsz * Hd;

    float *gates; __nv_bfloat16 *xhi, *xlo, *o0hi, *o0lo; uint32_t *wbhi, *wblo;
    cudaGetSymbolAddress((void**)&gates, g_gates);
    cudaGetSymbolAddress((void**)&xhi,  g_xhi);
    cudaGetSymbolAddress((void**)&xlo,  g_xlo);
    cudaGetSymbolAddress((void**)&o0hi, g_o0hi);
    cudaGetSymbolAddress((void**)&o0lo, g_o0lo);
    cudaGetSymbolAddress((void**)&wbhi, g_wbhi);
    cudaGetSymbolAddress((void**)&wblo, g_wblo);

    cudaFuncSetAttribute(conv_gemm<1024>,
                         cudaFuncAttributeMaxDynamicSharedMemorySize, SMEM_TOTAL);
    cudaFuncSetAttribute(conv_gemm<2048>,
                         cudaFuncAttributeMaxDynamicSharedMemorySize, SMEM_TOTAL);

    // ---- layer 0 ----
    prep_x<<<8192, 256>>>((const float4*)x, (uint32_t*)xhi, (uint32_t*)xlo);
    prep_w<<<dim3(32, 96), 256>>>(w0f, wbhi, wblo, 1024, 0);
    prep_w<<<dim3(32, 96), 256>>>(w0r, wbhi, wblo, 1024, 3072);
    conv_gemm<1024><<<dim3(48, 64), 256, SMEM_TOTAL>>>(xhi, xlo, wbhi, wblo,
                                                       b0f, b0r, gates);
    scan2<true><<<dim3(32, 2), 256>>>(gates, nullptr, o0hi, o0lo, hid, cel);
    // ---- layer 1 ----
    prep_w<<<dim3(64, 96), 256>>>(w1f, wbhi, wblo, 2048, 0);
    prep_w<<<dim3(64, 96), 256>>>(w1r, wbhi, wblo, 2048, 3072);
    conv_gemm<2048><<<dim3(48, 64), 256, SMEM_TOTAL>>>(o0hi, o0lo, wbhi, wblo,
                                                       b1f, b1r, gates);
    scan2<false><<<dim3(32, 2), 256>>>(gates, out1, nullptr, nullptr,
                                       hid + 16384, cel + 16384);
}

// round 6
// speedup vs baseline: 1.1764x; 1.1109x over previous
#include <cuda_runtime.h>
#include <cuda_bf16.h>
#include <cstdint>

#define Bsz  8
#define Tlen 1024
#define Hd   1024
#define NG   6144   // fused fwd+rev gate width: [f|o|z]fwd [f|o|z]rev

// ---------------- device scratch (no allocation allowed) -------------------
__device__ float          g_gates[(size_t)Bsz * Tlen * NG];        // 201 MB
__device__ __nv_bfloat16  g_xhi [(size_t)Bsz * Tlen * 1024];
__device__ __nv_bfloat16  g_xlo [(size_t)Bsz * Tlen * 1024];
__device__ __nv_bfloat16  g_o0hi[(size_t)Bsz * Tlen * 2048];
__device__ __nv_bfloat16  g_o0lo[(size_t)Bsz * Tlen * 2048];
__device__ __nv_bfloat16  g_wbhi[(size_t)6144 * NG];   // k-major bf16 [3C][6144]
__device__ __nv_bfloat16  g_wblo[(size_t)6144 * NG];

// ---------------------------------------------------------------------------
__device__ __forceinline__ void split2(float a, float b, uint32_t& hp, uint32_t& lp)
{
    __nv_bfloat16 ha = __float2bfloat16(a), hb = __float2bfloat16(b);
    float la = a - __bfloat162float(ha);
    float lb = b - __bfloat162float(hb);
    __nv_bfloat162 hv; hv.x = ha; hv.y = hb;
    __nv_bfloat162 lv; lv.x = __float2bfloat16(la); lv.y = __float2bfloat16(lb);
    hp = *(uint32_t*)&hv; lp = *(uint32_t*)&lv;
}

// split x (fp32) into hi/lo bf16 planes, 4 elems/thread
__global__ void prep_x(const float4* __restrict__ x,
                       uint32_t* __restrict__ hi, uint32_t* __restrict__ lo)
{
    int i = blockIdx.x * blockDim.x + threadIdx.x;   // over float4s
    float4 v = x[i];
    uint32_t h0, l0, h1, l1;
    split2(v.x, v.y, h0, l0);
    split2(v.z, v.w, h1, l1);
    ((uint2*)hi)[i] = make_uint2(h0, h1);
    ((uint2*)lo)[i] = make_uint2(l0, l1);
}

// ---------------------------------------------------------------------------
// weight prep: w [3072, C, 3] fp32 -> hi/lo bf16 planes [3C][6144], k-major:
// row r = tap*C + c, col = colbase + j.
// ---------------------------------------------------------------------------
__global__ void prep_w(const float* __restrict__ w,
                       __nv_bfloat16* __restrict__ wbhi,
                       __nv_bfloat16* __restrict__ wblo,
                       int C, int colbase)
{
    __shared__ float sm[32][97];
    const int tid = threadIdx.x;
    const int cb = blockIdx.x;   // c-block of 32 channels (96 floats per gate)
    const int jb = blockIdx.y;   // j-block of 32 gates

    for (int i = tid; i < 32 * 96; i += 256) {
        int j = i / 96, q = i % 96;
        sm[j][q] = w[(size_t)(jb * 32 + j) * 3 * C + cb * 96 + q];
    }
    __syncthreads();

    // 1536 items: (c_local 0..31) x (tap 0..2) x (j-pair 0..15)
    for (int i = tid; i < 1536; i += 256) {
        int jp = i & 15;
        int tap = (i >> 4) % 3;
        int cl  = i / 48;
        int q   = cl * 3 + tap;
        float x0 = sm[jp * 2][q];
        float x1 = sm[jp * 2 + 1][q];
        uint32_t hp, lp;
        split2(x0, x1, hp, lp);
        size_t r = (size_t)tap * C + cb * 32 + cl;
        size_t off = r * NG + colbase + jb * 32 + jp * 2;
        *(uint32_t*)&wbhi[off] = hp;
        *(uint32_t*)&wblo[off] = lp;
    }
}

// ---------------------------------------------------------------------------
__device__ __forceinline__ void cp_async16(uint32_t smem, const void* gmem, int bytes)
{
    asm volatile("cp.async.cg.shared.global [%0], [%1], 16, %2;\n"
                 :: "r"(smem), "l"(gmem), "r"(bytes));
}
__device__ __forceinline__ void cp_commit()
{
    asm volatile("cp.async.commit_group;\n" ::: "memory");
}
template <int N>
__device__ __forceinline__ void cp_wait()
{
    asm volatile("cp.async.wait_group %0;\n" :: "n"(N) : "memory");
}

#define MMA_BF16(acc, a, b0, b1)                                              \
    asm volatile("mma.sync.aligned.m16n8k16.row.col.f32.bf16.bf16.f32 "       \
                 "{%0,%1,%2,%3}, {%4,%5,%6,%7}, {%8,%9}, {%0,%1,%2,%3};\n"    \
                 : "+f"(acc[0]), "+f"(acc[1]), "+f"(acc[2]), "+f"(acc[3])     \
                 : "r"(a[0]), "r"(a[1]), "r"(a[2]), "r"(a[3]),                \
                   "r"(b0), "r"(b1));

#define LDSM_X4(r, addr)                                                      \
    asm volatile("ldmatrix.sync.aligned.m8n8.x4.shared.b16 "                  \
                 "{%0,%1,%2,%3}, [%4];"                                       \
                 : "=r"((r)[0]), "=r"((r)[1]), "=r"((r)[2]), "=r"((r)[3])     \
                 : "r"(addr));

#define LDSM_X4T(r, addr)                                                     \
    asm volatile("ldmatrix.sync.aligned.m8n8.x4.trans.shared.b16 "            \
                 "{%0,%1,%2,%3}, [%4];"                                       \
                 : "=r"((r)[0]), "=r"((r)[1]), "=r"((r)[2]), "=r"((r)[3])     \
                 : "r"(addr));

// ---------------------------------------------------------------------------
// bf16x3 emulated-fp32 conv(K=3)-as-GEMM + bias + activation.
// ldmatrix fragment loads, double-buffered cp.async, ONE barrier per BK tile.
// BM=128 BN=128 BK=32, 256 threads, warp tile 32x64 (4x2 warps)
// ---------------------------------------------------------------------------
// per-stage smem (bytes): Ash[128][40]bf16=10240 | Asl 10240 |
//                         Bsh[32][136]bf16=8704  | Bsl 8704
#define ST_ASL 10240
#define ST_BSH 20480
#define ST_BSL 29184
#define ST_SZ  37888
#define SMEM_TOTAL (2 * ST_SZ)

template <int C>
__global__ void __launch_bounds__(256, 2) conv_gemm(
    const __nv_bfloat16* __restrict__ Ahi,
    const __nv_bfloat16* __restrict__ Alo,
    const __nv_bfloat16* __restrict__ Bhi_,
    const __nv_bfloat16* __restrict__ Blo_,
    const float* __restrict__ biasF,
    const float* __restrict__ biasR,
    float* __restrict__ gates)
{
    extern __shared__ char smraw[];

    const int tid  = threadIdx.x;
    const int lane = tid & 31;
    const int warp = tid >> 5;
    const int wm   = warp & 3;
    const int wn   = warp >> 2;
    const int gp   = lane >> 2;
    const int tg   = lane & 3;

    const int row0 = blockIdx.y << 7;
    const int col0 = blockIdx.x << 7;
    const int t0   = row0 & (Tlen - 1);
    const __nv_bfloat16* Ahb = Ahi + (size_t)(row0 - t0) * C;
    const __nv_bfloat16* Alb = Alo + (size_t)(row0 - t0) * C;

    float acc[2][8][4];
#pragma unroll
    for (int a = 0; a < 2; a++)
#pragma unroll
        for (int b = 0; b < 8; b++)
#pragma unroll
            for (int c = 0; c < 4; c++) acc[a][b][c] = 0.f;

    const int a_m = tid >> 1;            // 0..127
    const int a_c = (tid & 1) << 4;      // 0 / 16 (bf16 elems)

    uint32_t sbase;
    asm("{ .reg .u64 t; cvta.to.shared.u64 t, %1; cvt.u32.u64 %0, t; }"
        : "=r"(sbase) : "l"(smraw));

    const int NKt = 3 * C / 32;

    // ---- stage loader ----
    auto load_stage = [&](int kt, int s) {
        const int kbase = kt << 5;
        const uint32_t st = sbase + s * ST_SZ;
        // A tile (hi+lo): rows m, 32 k-elems (one tap)
        {
            const int tap   = kbase / C;
            const int cbase = kbase - tap * C;
            int stt = t0 + a_m + tap - 1;
            int ok  = (stt >= 0) && (stt < Tlen);
            int stc = ok ? stt : 0;
            const __nv_bfloat16* srcH = Ahb + (size_t)stc * C + cbase + a_c;
            const __nv_bfloat16* srcL = Alb + (size_t)stc * C + cbase + a_c;
            uint32_t dA = st + (uint32_t)(a_m * 40 + a_c) * 2;
            cp_async16(dA,               srcH,     ok ? 16 : 0);
            cp_async16(dA + 16,          srcH + 8, ok ? 16 : 0);
            cp_async16(dA + ST_ASL,      srcL,     ok ? 16 : 0);
            cp_async16(dA + ST_ASL + 16, srcL + 8, ok ? 16 : 0);
        }
        // B tile (hi+lo): k-major [32][128] bf16, row pad to 136
        {
#pragma unroll
            for (int cc = 0; cc < 2; cc++) {
                int c = tid + cc * 256;          // 0..511 chunks of 16B
                int row = c >> 4;
                int off = (c & 15) << 3;         // bf16 elems
                size_t srcOff = (size_t)(kbase + row) * NG + col0 + off;
                uint32_t dB = st + ST_BSH + (uint32_t)(row * 136 + off) * 2;
                cp_async16(dB,                     Bhi_ + srcOff, 16);
                cp_async16(dB + (ST_BSL - ST_BSH), Blo_ + srcOff, 16);
            }
        }
    };

    load_stage(0, 0);
    cp_commit();

    const int lr = lane & 15;
    const int lh = lane >> 4;

    for (int kt = 0; kt < NKt; ++kt) {
        const int s = kt & 1;
        cp_wait<0>();
        __syncthreads();   // stage s arrived; stage s^1 fully consumed by all

        if (kt + 1 < NKt) {
            load_stage(kt + 1, s ^ 1);
            cp_commit();
        }

        const uint32_t stA  = sbase + s * ST_SZ;
        const uint32_t stAl = stA + ST_ASL;
        const uint32_t stB  = stA + ST_BSH;
        const uint32_t stBl = stA + ST_BSL;

#pragma unroll
        for (int ks = 0; ks < 2; ks++) {
            uint32_t ah[2][4], al[2][4];
            uint32_t aoff = (uint32_t)((wm * 32 + lr) * 40 + ks * 16 + lh * 8) * 2;
            LDSM_X4(ah[0], stA  + aoff);
            LDSM_X4(ah[1], stA  + aoff + 1280);   // +16 rows * 40 * 2B
            LDSM_X4(al[0], stAl + aoff);
            LDSM_X4(al[1], stAl + aoff + 1280);

#pragma unroll
            for (int np = 0; np < 4; np++) {      // each np = 16 n-cols (2 nj)
                uint32_t bh[4], bl[4];
                uint32_t boff = (uint32_t)((ks * 16 + lr) * 136 +
                                           wn * 64 + np * 16 + lh * 8) * 2;
                LDSM_X4T(bh, stB  + boff);
                LDSM_X4T(bl, stBl + boff);
                const int n0 = np * 2, n1 = np * 2 + 1;
                // term 1: lo*hi
                MMA_BF16(acc[0][n0], al[0], bh[0], bh[1]);
                MMA_BF16(acc[1][n0], al[1], bh[0], bh[1]);
                MMA_BF16(acc[0][n1], al[0], bh[2], bh[3]);
                MMA_BF16(acc[1][n1], al[1], bh[2], bh[3]);
                // term 2: hi*lo
                MMA_BF16(acc[0][n0], ah[0], bl[0], bl[1]);
                MMA_BF16(acc[1][n0], ah[1], bl[0], bl[1]);
                MMA_BF16(acc[0][n1], ah[0], bl[2], bl[3]);
                MMA_BF16(acc[1][n1], ah[1], bl[2], bl[3]);
                // term 3: hi*hi
                MMA_BF16(acc[0][n0], ah[0], bh[0], bh[1]);
                MMA_BF16(acc[1][n0], ah[1], bh[0], bh[1]);
                MMA_BF16(acc[0][n1], ah[0], bh[2], bh[3]);
                MMA_BF16(acc[1][n1], ah[1], bh[2], bh[3]);
            }
        }
    }

    // ---- epilogue: bias + activation ----
    const int  dircol = (col0 >= 3072) ? 1 : 0;
    const float* bias = dircol ? biasR : biasF;
    const int  lcol0  = col0 - dircol * 3072;
    const bool ztan   = (lcol0 >= 2048);   // z section -> tanh, else sigmoid

#pragma unroll
    for (int mi = 0; mi < 2; mi++) {
        int r0g = row0 + wm * 32 + mi * 16 + gp;
#pragma unroll
        for (int ni = 0; ni < 8; ni++) {
            int cl  = lcol0 + wn * 64 + ni * 8 + tg * 2;   // bias index
            int cg  = col0  + wn * 64 + ni * 8 + tg * 2;   // global gate col
            float b0v = bias[cl], b1v = bias[cl + 1];
            float v[4] = { acc[mi][ni][0] + b0v, acc[mi][ni][1] + b1v,
                           acc[mi][ni][2] + b0v, acc[mi][ni][3] + b1v };
#pragma unroll
            for (int j = 0; j < 4; j++) {
                if (ztan) v[j] = 1.f - __fdividef(2.f, __expf(2.f * v[j]) + 1.f);
                else      v[j] = __fdividef(1.f, 1.f + __expf(-v[j]));
            }
            *(float2*)(gates + (size_t)r0g * NG + cg)       = make_float2(v[0], v[1]);
            *(float2*)(gates + (size_t)(r0g + 8) * NG + cg) = make_float2(v[2], v[3]);
        }
    }
}

// ---------------------------------------------------------------------------
// fo-pool scan, both directions via blockIdx.y.
// c_t = f*c_{t-1} + (1-f)*z ;  h_t = c_t * o_t
// L0: write h as hi/lo bf16 planes [B*T, 2048]; L1: write fp32 to d_out.
// ---------------------------------------------------------------------------
template <bool L0>
__global__ void scan2(const float* __restrict__ gates,
                      float* __restrict__ out_f32,
                      __nv_bfloat16* __restrict__ ohi,
                      __nv_bfloat16* __restrict__ olo,
                      float* __restrict__ hid,
                      float* __restrict__ cel)
{
    const int dir = blockIdx.y;
    const int gid = blockIdx.x * blockDim.x + threadIdx.x;   // 0..8191
    const int b = gid >> 10, h = gid & 1023;
    const float* gb = gates + (size_t)b * Tlen * NG + dir * 3072 + h;
    const size_t obase = (size_t)b * Tlen * 2048 + dir * 1024 + h;
    float c = 0.f;

    auto emit = [&](int t, float hv) {
        size_t idx = obase + (size_t)t * 2048;
        if (L0) {
            __nv_bfloat16 hh = __float2bfloat16(hv);
            ohi[idx] = hh;
            olo[idx] = __float2bfloat16(hv - __bfloat162float(hh));
        } else {
            out_f32[idx] = hv;
        }
    };

    if (dir == 0) {
        float hl = 0.f;
        for (int tt = 0; tt < Tlen; tt += 8) {
            float fv[8], ov[8], zv[8];
#pragma unroll
            for (int i = 0; i < 8; i++) {
                size_t o_ = (size_t)(tt + i) * NG;
                fv[i] = gb[o_]; ov[i] = gb[o_ + 1024]; zv[i] = gb[o_ + 2048];
            }
#pragma unroll
            for (int i = 0; i < 8; i++) {
                c = fmaf(fv[i], c - zv[i], zv[i]);
                hl = c * ov[i];
                emit(tt + i, hl);
            }
        }
        hid[b * 2048 + h] = hl;
        cel[b * 2048 + h] = c;
    } else {
        float cfirst = 0.f, hfirst = 0.f;
        for (int tt = Tlen - 8; tt >= 0; tt -= 8) {
            float fv[8], ov[8], zv[8];
#pragma unroll
            for (int i = 0; i < 8; i++) {
                size_t o_ = (size_t)(tt + i) * NG;
                fv[i] = gb[o_]; ov[i] = gb[o_ + 1024]; zv[i] = gb[o_ + 2048];
            }
#pragma unroll
            for (int i = 7; i >= 0; i--) {
                c = fmaf(fv[i], c - zv[i], zv[i]);
                float hv = c * ov[i];
                emit(tt + i, hv);
                if (tt + i == Tlen - 1) { cfirst = c; hfirst = hv; }
            }
        }
        hid[1024 + b * 2048 + h] = hfirst;
        cel[1024 + b * 2048 + h] = cfirst;
    }
}

// ---------------------------------------------------------------------------
extern "C" void kernel_launch(void* const* d_in, const int* in_sizes, int n_in,
                              void* d_out, int out_size)
{
    const float* x   = (const float*)d_in[0];
    const float* w0f = (const float*)d_in[2];
    const float* b0f = (const float*)d_in[3];
    const float* w0r = (const float*)d_in[4];
    const float* b0r = (const float*)d_in[5];
    const float* w1f = (const float*)d_in[6];
    const float* b1f = (const float*)d_in[7];
    const float* w1r = (const float*)d_in[8];
    const float* b1r = (const float*)d_in[9];

    float* out1 = (float*)d_out;                         // [B,T,2H]
    float* hid  = out1 + (size_t)Bsz * Tlen * 2 * Hd;    // [4,B,H]
    float* cel  = hid + 4 * Bsz * Hd;

    float *gates; __nv_bfloat16 *xhi, *xlo, *o0hi, *o0lo, *wbhi, *wblo;
    cudaGetSymbolAddress((void**)&gates, g_gates);
    cudaGetSymbolAddress((void**)&xhi,  g_xhi);
    cudaGetSymbolAddress((void**)&xlo,  g_xlo);
    cudaGetSymbolAddress((void**)&o0hi, g_o0hi);
    cudaGetSymbolAddress((void**)&o0lo, g_o0lo);
    cudaGetSymbolAddress((void**)&wbhi, g_wbhi);
    cudaGetSymbolAddress((void**)&wblo, g_wblo);

    cudaFuncSetAttribute(conv_gemm<1024>,
                         cudaFuncAttributeMaxDynamicSharedMemorySize, SMEM_TOTAL);
    cudaFuncSetAttribute(conv_gemm<2048>,
                         cudaFuncAttributeMaxDynamicSharedMemorySize, SMEM_TOTAL);

    // ---- layer 0 ----
    prep_x<<<8192, 256>>>((const float4*)x, (uint32_t*)xhi, (uint32_t*)xlo);
    prep_w<<<dim3(32, 96), 256>>>(w0f, wbhi, wblo, 1024, 0);
    prep_w<<<dim3(32, 96), 256>>>(w0r, wbhi, wblo, 1024, 3072);
    conv_gemm<1024><<<dim3(48, 64), 256, SMEM_TOTAL>>>(xhi, xlo, wbhi, wblo,
                                                       b0f, b0r, gates);
    scan2<true><<<dim3(32, 2), 256>>>(gates, nullptr, o0hi, o0lo, hid, cel);
    // ---- layer 1 ----
    prep_w<<<dim3(64, 96), 256>>>(w1f, wbhi, wblo, 2048, 0);
    prep_w<<<dim3(64, 96), 256>>>(w1r, wbhi, wblo, 2048, 3072);
    conv_gemm<2048><<<dim3(48, 64), 256, SMEM_TOTAL>>>(o0hi, o0lo, wbhi, wblo,
                                                       b1f, b1r, gates);
    scan2<false><<<dim3(32, 2), 256>>>(gates, out1, nullptr, nullptr,
                                       hid + 16384, cel + 16384);
}

// round 7
// speedup vs baseline: 1.1858x; 1.0080x over previous
#include <cuda_runtime.h>
#include <cuda_bf16.h>
#include <cstdint>

#define Bsz  8
#define Tlen 1024
#define Hd   1024
#define NG   6144   // fused fwd+rev gate width: [f|o|z]fwd [f|o|z]rev

// ---------------- device scratch (no allocation allowed) -------------------
__device__ float          g_gates[(size_t)Bsz * Tlen * NG];        // 201 MB
__device__ __nv_bfloat16  g_xhi [(size_t)Bsz * Tlen * 1024];
__device__ __nv_bfloat16  g_xlo [(size_t)Bsz * Tlen * 1024];
__device__ __nv_bfloat16  g_o0hi[(size_t)Bsz * Tlen * 2048];
__device__ __nv_bfloat16  g_o0lo[(size_t)Bsz * Tlen * 2048];
__device__ __nv_bfloat16  g_wbhi[(size_t)6144 * NG];   // k-major bf16 [3C][6144]
__device__ __nv_bfloat16  g_wblo[(size_t)6144 * NG];

// ---------------------------------------------------------------------------
__device__ __forceinline__ void split2(float a, float b, uint32_t& hp, uint32_t& lp)
{
    __nv_bfloat16 ha = __float2bfloat16(a), hb = __float2bfloat16(b);
    float la = a - __bfloat162float(ha);
    float lb = b - __bfloat162float(hb);
    __nv_bfloat162 hv; hv.x = ha; hv.y = hb;
    __nv_bfloat162 lv; lv.x = __float2bfloat16(la); lv.y = __float2bfloat16(lb);
    hp = *(uint32_t*)&hv; lp = *(uint32_t*)&lv;
}

__global__ void prep_x(const float4* __restrict__ x,
                       uint32_t* __restrict__ hi, uint32_t* __restrict__ lo)
{
    int i = blockIdx.x * blockDim.x + threadIdx.x;
    float4 v = x[i];
    uint32_t h0, l0, h1, l1;
    split2(v.x, v.y, h0, l0);
    split2(v.z, v.w, h1, l1);
    ((uint2*)hi)[i] = make_uint2(h0, h1);
    ((uint2*)lo)[i] = make_uint2(l0, l1);
}

// weight prep: w [3072, C, 3] fp32 -> hi/lo bf16 planes [3C][6144], k-major
__global__ void prep_w(const float* __restrict__ w,
                       __nv_bfloat16* __restrict__ wbhi,
                       __nv_bfloat16* __restrict__ wblo,
                       int C, int colbase)
{
    __shared__ float sm[32][97];
    const int tid = threadIdx.x;
    const int cb = blockIdx.x;
    const int jb = blockIdx.y;

    for (int i = tid; i < 32 * 96; i += 256) {
        int j = i / 96, q = i % 96;
        sm[j][q] = w[(size_t)(jb * 32 + j) * 3 * C + cb * 96 + q];
    }
    __syncthreads();

    for (int i = tid; i < 1536; i += 256) {
        int jp = i & 15;
        int tap = (i >> 4) % 3;
        int cl  = i / 48;
        int q   = cl * 3 + tap;
        uint32_t hp, lp;
        split2(sm[jp * 2][q], sm[jp * 2 + 1][q], hp, lp);
        size_t r = (size_t)tap * C + cb * 32 + cl;
        size_t off = r * NG + colbase + jb * 32 + jp * 2;
        *(uint32_t*)&wbhi[off] = hp;
        *(uint32_t*)&wblo[off] = lp;
    }
}

// ---------------------------------------------------------------------------
__device__ __forceinline__ void cp_async16(uint32_t smem, const void* gmem, int bytes)
{
    asm volatile("cp.async.cg.shared.global [%0], [%1], 16, %2;\n"
                 :: "r"(smem), "l"(gmem), "r"(bytes));
}
__device__ __forceinline__ void cp_commit()
{
    asm volatile("cp.async.commit_group;\n" ::: "memory");
}
template <int N>
__device__ __forceinline__ void cp_wait()
{
    asm volatile("cp.async.wait_group %0;\n" :: "n"(N) : "memory");
}

#define MMA_BF16(acc, a, b0, b1)                                              \
    asm volatile("mma.sync.aligned.m16n8k16.row.col.f32.bf16.bf16.f32 "       \
                 "{%0,%1,%2,%3}, {%4,%5,%6,%7}, {%8,%9}, {%0,%1,%2,%3};\n"    \
                 : "+f"(acc[0]), "+f"(acc[1]), "+f"(acc[2]), "+f"(acc[3])     \
                 : "r"(a[0]), "r"(a[1]), "r"(a[2]), "r"(a[3]),                \
                   "r"(b0), "r"(b1));

#define LDSM_X4(r, addr)                                                      \
    asm volatile("ldmatrix.sync.aligned.m8n8.x4.shared.b16 "                  \
                 "{%0,%1,%2,%3}, [%4];"                                       \
                 : "=r"((r)[0]), "=r"((r)[1]), "=r"((r)[2]), "=r"((r)[3])     \
                 : "r"(addr));

#define LDSM_X4T(r, addr)                                                     \
    asm volatile("ldmatrix.sync.aligned.m8n8.x4.trans.shared.b16 "            \
                 "{%0,%1,%2,%3}, [%4];"                                       \
                 : "=r"((r)[0]), "=r"((r)[1]), "=r"((r)[2]), "=r"((r)[3])     \
                 : "r"(addr));

// ---------------------------------------------------------------------------
// bf16x3 conv-as-GEMM: 3-stage cp.async pipeline (wait_group<=1), full
// fragment preload per k16 step, term-outermost MMA order (16 indep/term).
// BM=128 BN=128 BK=32, 256 threads, warp tile 32x64.
// ---------------------------------------------------------------------------
#define ST_ASL 10240
#define ST_BSH 20480
#define ST_BSL 29184
#define ST_SZ  37888
#define SMEM_TOTAL (3 * ST_SZ)

template <int C>
__global__ void __launch_bounds__(256, 2) conv_gemm(
    const __nv_bfloat16* __restrict__ Ahi,
    const __nv_bfloat16* __restrict__ Alo,
    const __nv_bfloat16* __restrict__ Bhi_,
    const __nv_bfloat16* __restrict__ Blo_,
    const float* __restrict__ biasF,
    const float* __restrict__ biasR,
    float* __restrict__ gates)
{
    extern __shared__ char smraw[];

    const int tid  = threadIdx.x;
    const int lane = tid & 31;
    const int warp = tid >> 5;
    const int wm   = warp & 3;
    const int wn   = warp >> 2;
    const int gp   = lane >> 2;
    const int tg   = lane & 3;

    const int row0 = blockIdx.y << 7;
    const int col0 = blockIdx.x << 7;
    const int t0   = row0 & (Tlen - 1);
    const __nv_bfloat16* Ahb = Ahi + (size_t)(row0 - t0) * C;
    const __nv_bfloat16* Alb = Alo + (size_t)(row0 - t0) * C;

    float acc[2][8][4];
#pragma unroll
    for (int a = 0; a < 2; a++)
#pragma unroll
        for (int b = 0; b < 8; b++)
#pragma unroll
            for (int c = 0; c < 4; c++) acc[a][b][c] = 0.f;

    const int a_m = tid >> 1;
    const int a_c = (tid & 1) << 4;

    uint32_t sbase;
    asm("{ .reg .u64 t; cvta.to.shared.u64 t, %1; cvt.u32.u64 %0, t; }"
        : "=r"(sbase) : "l"(smraw));

    const int NKt = 3 * C / 32;

    auto load_stage = [&](int kt, int st_idx) {
        const int kbase = kt << 5;
        const uint32_t st = sbase + st_idx * ST_SZ;
        {
            const int tap   = kbase / C;
            const int cbase = kbase - tap * C;
            int stt = t0 + a_m + tap - 1;
            int ok  = (stt >= 0) && (stt < Tlen);
            int stc = ok ? stt : 0;
            const __nv_bfloat16* srcH = Ahb + (size_t)stc * C + cbase + a_c;
            const __nv_bfloat16* srcL = Alb + (size_t)stc * C + cbase + a_c;
            uint32_t dA = st + (uint32_t)(a_m * 40 + a_c) * 2;
            cp_async16(dA,               srcH,     ok ? 16 : 0);
            cp_async16(dA + 16,          srcH + 8, ok ? 16 : 0);
            cp_async16(dA + ST_ASL,      srcL,     ok ? 16 : 0);
            cp_async16(dA + ST_ASL + 16, srcL + 8, ok ? 16 : 0);
        }
        {
#pragma unroll
            for (int cc = 0; cc < 2; cc++) {
                int c = tid + cc * 256;
                int row = c >> 4;
                int off = (c & 15) << 3;
                size_t srcOff = (size_t)(kbase + row) * NG + col0 + off;
                uint32_t dB = st + ST_BSH + (uint32_t)(row * 136 + off) * 2;
                cp_async16(dB,                     Bhi_ + srcOff, 16);
                cp_async16(dB + (ST_BSL - ST_BSH), Blo_ + srcOff, 16);
            }
        }
    };

    load_stage(0, 0);
    cp_commit();
    load_stage(1, 1);
    cp_commit();

    const int lr = lane & 15;
    const int lh = lane >> 4;

    for (int kt = 0; kt < NKt; ++kt) {
        const int s = kt % 3;
        cp_wait<1>();      // stage s was issued two tiles ago -> done
        __syncthreads();   // stage (s+2)%3 fully consumed by all warps

        if (kt + 2 < NKt) {
            load_stage(kt + 2, (kt + 2) % 3);
            cp_commit();
        }

        const uint32_t stA  = sbase + s * ST_SZ;
        const uint32_t stAl = stA + ST_ASL;
        const uint32_t stB  = stA + ST_BSH;
        const uint32_t stBl = stA + ST_BSL;

#pragma unroll
        for (int ks = 0; ks < 2; ks++) {
            uint32_t ah[2][4], al[2][4];
            uint32_t aoff = (uint32_t)((wm * 32 + lr) * 40 + ks * 16 + lh * 8) * 2;
            LDSM_X4(ah[0], stA  + aoff);
            LDSM_X4(ah[1], stA  + aoff + 1280);   // +16 rows * 80B
            LDSM_X4(al[0], stAl + aoff);
            LDSM_X4(al[1], stAl + aoff + 1280);

            // B frags: LDSM_X4T at np fills regs for n8 groups 2np (r0,r1)
            // and 2np+1 (r2,r3) -> bh[16]/bl[16] hold 8 groups x 2 regs.
            uint32_t bh[16], bl[16];
#pragma unroll
            for (int np = 0; np < 4; np++) {
                uint32_t boff = (uint32_t)((ks * 16 + lr) * 136 +
                                           wn * 64 + np * 16 + lh * 8) * 2;
                LDSM_X4T(&bh[np * 4], stB  + boff);
                LDSM_X4T(&bl[np * 4], stBl + boff);
            }

            // term 1: lo*hi — 16 independent MMAs
#pragma unroll
            for (int ni = 0; ni < 8; ni++) {
                MMA_BF16(acc[0][ni], al[0], bh[ni * 2], bh[ni * 2 + 1]);
                MMA_BF16(acc[1][ni], al[1], bh[ni * 2], bh[ni * 2 + 1]);
            }
            // term 2: hi*lo
#pragma unroll
            for (int ni = 0; ni < 8; ni++) {
                MMA_BF16(acc[0][ni], ah[0], bl[ni * 2], bl[ni * 2 + 1]);
                MMA_BF16(acc[1][ni], ah[1], bl[ni * 2], bl[ni * 2 + 1]);
            }
            // term 3: hi*hi
#pragma unroll
            for (int ni = 0; ni < 8; ni++) {
                MMA_BF16(acc[0][ni], ah[0], bh[ni * 2], bh[ni * 2 + 1]);
                MMA_BF16(acc[1][ni], ah[1], bh[ni * 2], bh[ni * 2 + 1]);
            }
        }
    }

    // ---- epilogue: bias + activation ----
    const int  dircol = (col0 >= 3072) ? 1 : 0;
    const float* bias = dircol ? biasR : biasF;
    const int  lcol0  = col0 - dircol * 3072;
    const bool ztan   = (lcol0 >= 2048);

#pragma unroll
    for (int mi = 0; mi < 2; mi++) {
        int r0g = row0 + wm * 32 + mi * 16 + gp;
#pragma unroll
        for (int ni = 0; ni < 8; ni++) {
            int cl  = lcol0 + wn * 64 + ni * 8 + tg * 2;
            int cg  = col0  + wn * 64 + ni * 8 + tg * 2;
            float b0v = bias[cl], b1v = bias[cl + 1];
            float v[4] = { acc[mi][ni][0] + b0v, acc[mi][ni][1] + b1v,
                           acc[mi][ni][2] + b0v, acc[mi][ni][3] + b1v };
#pragma unroll
            for (int j = 0; j < 4; j++) {
                if (ztan) v[j] = 1.f - __fdividef(2.f, __expf(2.f * v[j]) + 1.f);
                else      v[j] = __fdividef(1.f, 1.f + __expf(-v[j]));
            }
            *(float2*)(gates + (size_t)r0g * NG + cg)       = make_float2(v[0], v[1]);
            *(float2*)(gates + (size_t)(r0g + 8) * NG + cg) = make_float2(v[2], v[3]);
        }
    }
}

// ---------------------------------------------------------------------------
// fo-pool scan, both directions via blockIdx.y.
// ---------------------------------------------------------------------------
template <bool L0>
__global__ void scan2(const float* __restrict__ gates,
                      float* __restrict__ out_f32,
                      __nv_bfloat16* __restrict__ ohi,
                      __nv_bfloat16* __restrict__ olo,
                      float* __restrict__ hid,
                      float* __restrict__ cel)
{
    const int dir = blockIdx.y;
    const int gid = blockIdx.x * blockDim.x + threadIdx.x;
    const int b = gid >> 10, h = gid & 1023;
    const float* gb = gates + (size_t)b * Tlen * NG + dir * 3072 + h;
    const size_t obase = (size_t)b * Tlen * 2048 + dir * 1024 + h;
    float c = 0.f;

    auto emit = [&](int t, float hv) {
        size_t idx = obase + (size_t)t * 2048;
        if (L0) {
            __nv_bfloat16 hh = __float2bfloat16(hv);
            ohi[idx] = hh;
            olo[idx] = __float2bfloat16(hv - __bfloat162float(hh));
        } else {
            out_f32[idx] = hv;
        }
    };

    if (dir == 0) {
        float hl = 0.f;
        for (int tt = 0; tt < Tlen; tt += 8) {
            float fv[8], ov[8], zv[8];
#pragma unroll
            for (int i = 0; i < 8; i++) {
                size_t o_ = (size_t)(tt + i) * NG;
                fv[i] = gb[o_]; ov[i] = gb[o_ + 1024]; zv[i] = gb[o_ + 2048];
            }
#pragma unroll
            for (int i = 0; i < 8; i++) {
                c = fmaf(fv[i], c - zv[i], zv[i]);
                hl = c * ov[i];
                emit(tt + i, hl);
            }
        }
        hid[b * 2048 + h] = hl;
        cel[b * 2048 + h] = c;
    } else {
        float cfirst = 0.f, hfirst = 0.f;
        for (int tt = Tlen - 8; tt >= 0; tt -= 8) {
            float fv[8], ov[8], zv[8];
#pragma unroll
            for (int i = 0; i < 8; i++) {
                size_t o_ = (size_t)(tt + i) * NG;
                fv[i] = gb[o_]; ov[i] = gb[o_ + 1024]; zv[i] = gb[o_ + 2048];
            }
#pragma unroll
            for (int i = 7; i >= 0; i--) {
                c = fmaf(fv[i], c - zv[i], zv[i]);
                float hv = c * ov[i];
                emit(tt + i, hv);
                if (tt + i == Tlen - 1) { cfirst = c; hfirst = hv; }
            }
        }
        hid[1024 + b * 2048 + h] = hfirst;
        cel[1024 + b * 2048 + h] = cfirst;
    }
}

// ---------------------------------------------------------------------------
extern "C" void kernel_launch(void* const* d_in, const int* in_sizes, int n_in,
                              void* d_out, int out_size)
{
    const float* x   = (const float*)d_in[0];
    const float* w0f = (const float*)d_in[2];
    const float* b0f = (const float*)d_in[3];
    const float* w0r = (const float*)d_in[4];
    const float* b0r = (const float*)d_in[5];
    const float* w1f = (const float*)d_in[6];
    const float* b1f = (const float*)d_in[7];
    const float* w1r = (const float*)d_in[8];
    const float* b1r = (const float*)d_in[9];

    float* out1 = (float*)d_out;                         // [B,T,2H]
    float* hid  = out1 + (size_t)Bsz * Tlen * 2 * Hd;    // [4,B,H]
    float* cel  = hid + 4 * Bsz * Hd;

    float *gates; __nv_bfloat16 *xhi, *xlo, *o0hi, *o0lo, *wbhi, *wblo;
    cudaGetSymbolAddress((void**)&gates, g_gates);
    cudaGetSymbolAddress((void**)&xhi,  g_xhi);
    cudaGetSymbolAddress((void**)&xlo,  g_xlo);
    cudaGetSymbolAddress((void**)&o0hi, g_o0hi);
    cudaGetSymbolAddress((void**)&o0lo, g_o0lo);
    cudaGetSymbolAddress((void**)&wbhi, g_wbhi);
    cudaGetSymbolAddress((void**)&wblo, g_wblo);

    cudaFuncSetAttribute(conv_gemm<1024>,
                         cudaFuncAttributeMaxDynamicSharedMemorySize, SMEM_TOTAL);
    cudaFuncSetAttribute(conv_gemm<2048>,
                         cudaFuncAttributeMaxDynamicSharedMemorySize, SMEM_TOTAL);

    // ---- layer 0 ----
    prep_x<<<8192, 256>>>((const float4*)x, (uint32_t*)xhi, (uint32_t*)xlo);
    prep_w<<<dim3(32, 96), 256>>>(w0f, wbhi, wblo, 1024, 0);
    prep_w<<<dim3(32, 96), 256>>>(w0r, wbhi, wblo, 1024, 3072);
    conv_gemm<1024><<<dim3(48, 64), 256, SMEM_TOTAL>>>(xhi, xlo, wbhi, wblo,
                                                       b0f, b0r, gates);
    scan2<true><<<dim3(32, 2), 256>>>(gates, nullptr, o0hi, o0lo, hid, cel);
    // ---- layer 1 ----
    prep_w<<<dim3(64, 96), 256>>>(w1f, wbhi, wblo, 2048, 0);
    prep_w<<<dim3(64, 96), 256>>>(w1r, wbhi, wblo, 2048, 3072);
    conv_gemm<2048><<<dim3(48, 64), 256, SMEM_TOTAL>>>(o0hi, o0lo, wbhi, wblo,
                                                       b1f, b1r, gates);
    scan2<false><<<dim3(32, 2), 256>>>(gates, out1, nullptr, nullptr,
                                       hid + 16384, cel + 16384);
}

// round 8
// speedup vs baseline: 1.2113x; 1.0215x over previous
#include <cuda_runtime.h>
#include <cuda_bf16.h>
#include <cstdint>

#define Bsz  8
#define Tlen 1024
#define Hd   1024
#define NG   6144   // fused fwd+rev gate width: [f|o|z]fwd [f|o|z]rev

// ---------------- device scratch (no allocation allowed) -------------------
__device__ float          g_gates[(size_t)Bsz * Tlen * NG];        // 201 MB
__device__ __nv_bfloat16  g_xhi [(size_t)Bsz * Tlen * 1024];
__device__ __nv_bfloat16  g_xlo [(size_t)Bsz * Tlen * 1024];
__device__ __nv_bfloat16  g_o0hi[(size_t)Bsz * Tlen * 2048];
__device__ __nv_bfloat16  g_o0lo[(size_t)Bsz * Tlen * 2048];
__device__ __nv_bfloat16  g_wbhi[(size_t)6144 * NG];   // k-major bf16 [3C][6144]
__device__ __nv_bfloat16  g_wblo[(size_t)6144 * NG];

// ---------------------------------------------------------------------------
__device__ __forceinline__ void split2(float a, float b, uint32_t& hp, uint32_t& lp)
{
    __nv_bfloat16 ha = __float2bfloat16(a), hb = __float2bfloat16(b);
    float la = a - __bfloat162float(ha);
    float lb = b - __bfloat162float(hb);
    __nv_bfloat162 hv; hv.x = ha; hv.y = hb;
    __nv_bfloat162 lv; lv.x = __float2bfloat16(la); lv.y = __float2bfloat16(lb);
    hp = *(uint32_t*)&hv; lp = *(uint32_t*)&lv;
}

__global__ void prep_x(const float4* __restrict__ x,
                       uint32_t* __restrict__ hi, uint32_t* __restrict__ lo)
{
    int i = blockIdx.x * blockDim.x + threadIdx.x;
    float4 v = x[i];
    uint32_t h0, l0, h1, l1;
    split2(v.x, v.y, h0, l0);
    split2(v.z, v.w, h1, l1);
    ((uint2*)hi)[i] = make_uint2(h0, h1);
    ((uint2*)lo)[i] = make_uint2(l0, l1);
}

// weight prep: w [3072, C, 3] fp32 -> hi/lo bf16 planes [3C][6144], k-major
__global__ void prep_w(const float* __restrict__ w,
                       __nv_bfloat16* __restrict__ wbhi,
                       __nv_bfloat16* __restrict__ wblo,
                       int C, int colbase)
{
    __shared__ float sm[32][97];
    const int tid = threadIdx.x;
    const int cb = blockIdx.x;
    const int jb = blockIdx.y;

    for (int i = tid; i < 32 * 96; i += 256) {
        int j = i / 96, q = i % 96;
        sm[j][q] = w[(size_t)(jb * 32 + j) * 3 * C + cb * 96 + q];
    }
    __syncthreads();

    for (int i = tid; i < 1536; i += 256) {
        int jp = i & 15;
        int tap = (i >> 4) % 3;
        int cl  = i / 48;
        int q   = cl * 3 + tap;
        uint32_t hp, lp;
        split2(sm[jp * 2][q], sm[jp * 2 + 1][q], hp, lp);
        size_t r = (size_t)tap * C + cb * 32 + cl;
        size_t off = r * NG + colbase + jb * 32 + jp * 2;
        *(uint32_t*)&wbhi[off] = hp;
        *(uint32_t*)&wblo[off] = lp;
    }
}

// ---------------------------------------------------------------------------
__device__ __forceinline__ void cp_async16(uint32_t smem, const void* gmem, int bytes)
{
    asm volatile("cp.async.cg.shared.global [%0], [%1], 16, %2;\n"
                 :: "r"(smem), "l"(gmem), "r"(bytes));
}
__device__ __forceinline__ void cp_commit()
{
    asm volatile("cp.async.commit_group;\n" ::: "memory");
}
template <int N>
__device__ __forceinline__ void cp_wait()
{
    asm volatile("cp.async.wait_group %0;\n" :: "n"(N) : "memory");
}

#define MMA_BF16(acc, a, b0, b1)                                              \
    asm volatile("mma.sync.aligned.m16n8k16.row.col.f32.bf16.bf16.f32 "       \
                 "{%0,%1,%2,%3}, {%4,%5,%6,%7}, {%8,%9}, {%0,%1,%2,%3};\n"    \
                 : "+f"(acc[0]), "+f"(acc[1]), "+f"(acc[2]), "+f"(acc[3])     \
                 : "r"(a[0]), "r"(a[1]), "r"(a[2]), "r"(a[3]),                \
                   "r"(b0), "r"(b1));

#define LDSM_X4(r, addr)                                                      \
    asm volatile("ldmatrix.sync.aligned.m8n8.x4.shared.b16 "                  \
                 "{%0,%1,%2,%3}, [%4];"                                       \
                 : "=r"((r)[0]), "=r"((r)[1]), "=r"((r)[2]), "=r"((r)[3])     \
                 : "r"(addr));

#define LDSM_X4T(r, addr)                                                     \
    asm volatile("ldmatrix.sync.aligned.m8n8.x4.trans.shared.b16 "            \
                 "{%0,%1,%2,%3}, [%4];"                                       \
                 : "=r"((r)[0]), "=r"((r)[1]), "=r"((r)[2]), "=r"((r)[3])     \
                 : "r"(addr));

// ---------------------------------------------------------------------------
// bf16x3 conv-as-GEMM, occupancy-optimized:
// BM=128 BN=96, 384 threads (4m x 3n warps), warp tile 32x32,
// 3-stage cp.async pipeline, single barrier per BK tile.
// 768 threads/SM (2 CTAs) = 6 warps/SMSP to cover LDSM bubbles.
// ---------------------------------------------------------------------------
// per-stage smem (bytes): Ash[128][40]bf16=10240 | Asl 10240 |
//                         Bsh[32][104]bf16=6656  | Bsl 6656    => 33792
#define ST_ASL 10240
#define ST_BSH 20480
#define ST_BSL 27136
#define ST_SZ  33792
#define SMEM_TOTAL (3 * ST_SZ)

template <int C>
__global__ void __launch_bounds__(384, 2) conv_gemm(
    const __nv_bfloat16* __restrict__ Ahi,
    const __nv_bfloat16* __restrict__ Alo,
    const __nv_bfloat16* __restrict__ Bhi_,
    const __nv_bfloat16* __restrict__ Blo_,
    const float* __restrict__ biasF,
    const float* __restrict__ biasR,
    float* __restrict__ gates)
{
    extern __shared__ char smraw[];

    const int tid  = threadIdx.x;          // 0..383
    const int lane = tid & 31;
    const int warp = tid >> 5;             // 0..11
    const int wm   = warp & 3;             // 0..3  (M)
    const int wn   = warp >> 2;            // 0..2  (N)
    const int gp   = lane >> 2;
    const int tg   = lane & 3;

    const int row0 = blockIdx.y << 7;
    const int col0 = blockIdx.x * 96;
    const int t0   = row0 & (Tlen - 1);
    const __nv_bfloat16* Ahb = Ahi + (size_t)(row0 - t0) * C;
    const __nv_bfloat16* Alb = Alo + (size_t)(row0 - t0) * C;

    float acc[2][4][4];
#pragma unroll
    for (int a = 0; a < 2; a++)
#pragma unroll
        for (int b = 0; b < 4; b++)
#pragma unroll
            for (int c = 0; c < 4; c++) acc[a][b][c] = 0.f;

    const int a_m = (tid & 255) >> 1;      // 0..127 (threads 0..255)
    const int a_c = (tid & 1) << 4;        // 0 / 16 (bf16 elems)
    const int b_row = tid / 12;            // 0..31
    const int b_off = (tid % 12) * 8;      // 0..88 (bf16 elems)

    uint32_t sbase;
    asm("{ .reg .u64 t; cvta.to.shared.u64 t, %1; cvt.u32.u64 %0, t; }"
        : "=r"(sbase) : "l"(smraw));

    const int NKt = 3 * C / 32;

    auto load_stage = [&](int kt, int st_idx) {
        const int kbase = kt << 5;
        const uint32_t st = sbase + st_idx * ST_SZ;
        // A tile (hi+lo): threads 0..255, 128 rows x 32 k-elems
        if (tid < 256) {
            const int tap   = kbase / C;
            const int cbase = kbase - tap * C;
            int stt = t0 + a_m + tap - 1;
            int ok  = (stt >= 0) && (stt < Tlen);
            int stc = ok ? stt : 0;
            const __nv_bfloat16* srcH = Ahb + (size_t)stc * C + cbase + a_c;
            const __nv_bfloat16* srcL = Alb + (size_t)stc * C + cbase + a_c;
            uint32_t dA = st + (uint32_t)(a_m * 40 + a_c) * 2;
            cp_async16(dA,               srcH,     ok ? 16 : 0);
            cp_async16(dA + 16,          srcH + 8, ok ? 16 : 0);
            cp_async16(dA + ST_ASL,      srcL,     ok ? 16 : 0);
            cp_async16(dA + ST_ASL + 16, srcL + 8, ok ? 16 : 0);
        }
        // B tile (hi+lo): 32 rows x 96 cols, one 16B chunk per thread/plane
        {
            size_t srcOff = (size_t)(kbase + b_row) * NG + col0 + b_off;
            uint32_t dB = st + ST_BSH + (uint32_t)(b_row * 104 + b_off) * 2;
            cp_async16(dB,                     Bhi_ + srcOff, 16);
            cp_async16(dB + (ST_BSL - ST_BSH), Blo_ + srcOff, 16);
        }
    };

    load_stage(0, 0);
    cp_commit();
    load_stage(1, 1);
    cp_commit();

    const int lr = lane & 15;
    const int lh = lane >> 4;

    for (int kt = 0; kt < NKt; ++kt) {
        const int s = kt % 3;
        cp_wait<1>();      // stage s (issued two tiles ago) is done
        __syncthreads();   // all warps finished compute of kt-1 -> buffer
                           // (kt+2)%3 (== kt-1's) is reusable

        if (kt + 2 < NKt) {
            load_stage(kt + 2, (kt + 2) % 3);
            cp_commit();
        }

        const uint32_t stA  = sbase + s * ST_SZ;
        const uint32_t stAl = stA + ST_ASL;
        const uint32_t stB  = stA + ST_BSH;
        const uint32_t stBl = stA + ST_BSL;

#pragma unroll
        for (int ks = 0; ks < 2; ks++) {
            uint32_t ah[2][4], al[2][4];
            uint32_t aoff = (uint32_t)((wm * 32 + lr) * 40 + ks * 16 + lh * 8) * 2;
            LDSM_X4(ah[0], stA  + aoff);
            LDSM_X4(ah[1], stA  + aoff + 1280);   // +16 rows * 80B
            LDSM_X4(al[0], stAl + aoff);
            LDSM_X4(al[1], stAl + aoff + 1280);

            // B frags: X4T at np fills n8 groups 2np (r0,r1), 2np+1 (r2,r3)
            uint32_t bh[8], bl[8];
#pragma unroll
            for (int np = 0; np < 2; np++) {
                uint32_t boff = (uint32_t)((ks * 16 + lr) * 104 +
                                           wn * 32 + np * 16 + lh * 8) * 2;
                LDSM_X4T(&bh[np * 4], stB  + boff);
                LDSM_X4T(&bl[np * 4], stBl + boff);
            }

            // term 1: lo*hi — 8 independent MMAs
#pragma unroll
            for (int ni = 0; ni < 4; ni++) {
                MMA_BF16(acc[0][ni], al[0], bh[ni * 2], bh[ni * 2 + 1]);
                MMA_BF16(acc[1][ni], al[1], bh[ni * 2], bh[ni * 2 + 1]);
            }
            // term 2: hi*lo
#pragma unroll
            for (int ni = 0; ni < 4; ni++) {
                MMA_BF16(acc[0][ni], ah[0], bl[ni * 2], bl[ni * 2 + 1]);
                MMA_BF16(acc[1][ni], ah[1], bl[ni * 2], bl[ni * 2 + 1]);
            }
            // term 3: hi*hi
#pragma unroll
            for (int ni = 0; ni < 4; ni++) {
                MMA_BF16(acc[0][ni], ah[0], bh[ni * 2], bh[ni * 2 + 1]);
                MMA_BF16(acc[1][ni], ah[1], bh[ni * 2], bh[ni * 2 + 1]);
            }
        }
    }

    // ---- epilogue: bias + activation (per-column act select) ----
    const int  dircol = (col0 >= 3072) ? 1 : 0;
    const float* bias = dircol ? biasR : biasF;
    const int  lcol0  = col0 - dircol * 3072;

#pragma unroll
    for (int mi = 0; mi < 2; mi++) {
        int r0g = row0 + wm * 32 + mi * 16 + gp;
#pragma unroll
        for (int ni = 0; ni < 4; ni++) {
            int cl  = lcol0 + wn * 32 + ni * 8 + tg * 2;   // bias/act index
            int cg  = col0  + wn * 32 + ni * 8 + tg * 2;   // global gate col
            const bool ztan = (cl >= 2048);                // z section -> tanh
            float b0v = bias[cl], b1v = bias[cl + 1];
            float v[4] = { acc[mi][ni][0] + b0v, acc[mi][ni][1] + b1v,
                           acc[mi][ni][2] + b0v, acc[mi][ni][3] + b1v };
#pragma unroll
            for (int j = 0; j < 4; j++) {
                if (ztan) v[j] = 1.f - __fdividef(2.f, __expf(2.f * v[j]) + 1.f);
                else      v[j] = __fdividef(1.f, 1.f + __expf(-v[j]));
            }
            *(float2*)(gates + (size_t)r0g * NG + cg)       = make_float2(v[0], v[1]);
            *(float2*)(gates + (size_t)(r0g + 8) * NG + cg) = make_float2(v[2], v[3]);
        }
    }
}

// ---------------------------------------------------------------------------
// fo-pool scan, both directions via blockIdx.y.
// ---------------------------------------------------------------------------
template <bool L0>
__global__ void scan2(const float* __restrict__ gates,
                      float* __restrict__ out_f32,
                      __nv_bfloat16* __restrict__ ohi,
                      __nv_bfloat16* __restrict__ olo,
                      float* __restrict__ hid,
                      float* __restrict__ cel)
{
    const int dir = blockIdx.y;
    const int gid = blockIdx.x * blockDim.x + threadIdx.x;
    const int b = gid >> 10, h = gid & 1023;
    const float* gb = gates + (size_t)b * Tlen * NG + dir * 3072 + h;
    const size_t obase = (size_t)b * Tlen * 2048 + dir * 1024 + h;
    float c = 0.f;

    auto emit = [&](int t, float hv) {
        size_t idx = obase + (size_t)t * 2048;
        if (L0) {
            __nv_bfloat16 hh = __float2bfloat16(hv);
            ohi[idx] = hh;
            olo[idx] = __float2bfloat16(hv - __bfloat162float(hh));
        } else {
            out_f32[idx] = hv;
        }
    };

    if (dir == 0) {
        float hl = 0.f;
        for (int tt = 0; tt < Tlen; tt += 8) {
            float fv[8], ov[8], zv[8];
#pragma unroll
            for (int i = 0; i < 8; i++) {
                size_t o_ = (size_t)(tt + i) * NG;
                fv[i] = gb[o_]; ov[i] = gb[o_ + 1024]; zv[i] = gb[o_ + 2048];
            }
#pragma unroll
            for (int i = 0; i < 8; i++) {
                c = fmaf(fv[i], c - zv[i], zv[i]);
                hl = c * ov[i];
                emit(tt + i, hl);
            }
        }
        hid[b * 2048 + h] = hl;
        cel[b * 2048 + h] = c;
    } else {
        float cfirst = 0.f, hfirst = 0.f;
        for (int tt = Tlen - 8; tt >= 0; tt -= 8) {
            float fv[8], ov[8], zv[8];
#pragma unroll
            for (int i = 0; i < 8; i++) {
                size_t o_ = (size_t)(tt + i) * NG;
                fv[i] = gb[o_]; ov[i] = gb[o_ + 1024]; zv[i] = gb[o_ + 2048];
            }
#pragma unroll
            for (int i = 7; i >= 0; i--) {
                c = fmaf(fv[i], c - zv[i], zv[i]);
                float hv = c * ov[i];
                emit(tt + i, hv);
                if (tt + i == Tlen - 1) { cfirst = c; hfirst = hv; }
            }
        }
        hid[1024 + b * 2048 + h] = hfirst;
        cel[1024 + b * 2048 + h] = cfirst;
    }
}

// ---------------------------------------------------------------------------
extern "C" void kernel_launch(void* const* d_in, const int* in_sizes, int n_in,
                              void* d_out, int out_size)
{
    const float* x   = (const float*)d_in[0];
    const float* w0f = (const float*)d_in[2];
    const float* b0f = (const float*)d_in[3];
    const float* w0r = (const float*)d_in[4];
    const float* b0r = (const float*)d_in[5];
    const float* w1f = (const float*)d_in[6];
    const float* b1f = (const float*)d_in[7];
    const float* w1r = (const float*)d_in[8];
    const float* b1r = (const float*)d_in[9];

    float* out1 = (float*)d_out;                         // [B,T,2H]
    float* hid  = out1 + (size_t)Bsz * Tlen * 2 * Hd;    // [4,B,H]
    float* cel  = hid + 4 * Bsz * Hd;

    float *gates; __nv_bfloat16 *xhi, *xlo, *o0hi, *o0lo, *wbhi, *wblo;
    cudaGetSymbolAddress((void**)&gates, g_gates);
    cudaGetSymbolAddress((void**)&xhi,  g_xhi);
    cudaGetSymbolAddress((void**)&xlo,  g_xlo);
    cudaGetSymbolAddress((void**)&o0hi, g_o0hi);
    cudaGetSymbolAddress((void**)&o0lo, g_o0lo);
    cudaGetSymbolAddress((void**)&wbhi, g_wbhi);
    cudaGetSymbolAddress((void**)&wblo, g_wblo);

    cudaFuncSetAttribute(conv_gemm<1024>,
                         cudaFuncAttributeMaxDynamicSharedMemorySize, SMEM_TOTAL);
    cudaFuncSetAttribute(conv_gemm<2048>,
                         cudaFuncAttributeMaxDynamicSharedMemorySize, SMEM_TOTAL);

    // ---- layer 0 ----
    prep_x<<<8192, 256>>>((const float4*)x, (uint32_t*)xhi, (uint32_t*)xlo);
    prep_w<<<dim3(32, 96), 256>>>(w0f, wbhi, wblo, 1024, 0);
    prep_w<<<dim3(32, 96), 256>>>(w0r, wbhi, wblo, 1024, 3072);
    conv_gemm<1024><<<dim3(64, 64), 384, SMEM_TOTAL>>>(xhi, xlo, wbhi, wblo,
                                                       b0f, b0r, gates);
    scan2<true><<<dim3(32, 2), 256>>>(gates, nullptr, o0hi, o0lo, hid, cel);
    // ---- layer 1 ----
    prep_w<<<dim3(64, 96), 256>>>(w1f, wbhi, wblo, 2048, 0);
    prep_w<<<dim3(64, 96), 256>>>(w1r, wbhi, wblo, 2048, 3072);
    conv_gemm<2048><<<dim3(64, 64), 384, SMEM_TOTAL>>>(o0hi, o0lo, wbhi, wblo,
                                                       b1f, b1r, gates);
    scan2<false><<<dim3(32, 2), 256>>>(gates, out1, nullptr, nullptr,
                                       hid + 16384, cel + 16384);
}

// round 9
// speedup vs baseline: 1.3381x; 1.1047x over previous
#include <cuda_runtime.h>
#include <cuda_bf16.h>
#include <cstdint>

#define Bsz  8
#define Tlen 1024
#define Hd   1024
#define NG   6144   // fused fwd+rev gate width: [f|o|z]fwd [f|o|z]rev

// ---------------- device scratch (no allocation allowed) -------------------
__device__ float          g_gates[(size_t)Bsz * Tlen * NG];        // 201 MB
__device__ __nv_bfloat16  g_xhi [(size_t)Bsz * Tlen * 1024];
__device__ __nv_bfloat16  g_xlo [(size_t)Bsz * Tlen * 1024];
__device__ __nv_bfloat16  g_o0hi[(size_t)Bsz * Tlen * 2048];
__device__ __nv_bfloat16  g_o0lo[(size_t)Bsz * Tlen * 2048];
__device__ __nv_bfloat16  g_wbhi[(size_t)6144 * NG];   // k-major bf16 [3C][6144]
__device__ __nv_bfloat16  g_wblo[(size_t)6144 * NG];

// ---------------------------------------------------------------------------
__device__ __forceinline__ void split2(float a, float b, uint32_t& hp, uint32_t& lp)
{
    __nv_bfloat16 ha = __float2bfloat16(a), hb = __float2bfloat16(b);
    float la = a - __bfloat162float(ha);
    float lb = b - __bfloat162float(hb);
    __nv_bfloat162 hv; hv.x = ha; hv.y = hb;
    __nv_bfloat162 lv; lv.x = __float2bfloat16(la); lv.y = __float2bfloat16(lb);
    hp = *(uint32_t*)&hv; lp = *(uint32_t*)&lv;
}

__global__ void prep_x(const float4* __restrict__ x,
                       uint32_t* __restrict__ hi, uint32_t* __restrict__ lo)
{
    int i = blockIdx.x * blockDim.x + threadIdx.x;
    float4 v = x[i];
    uint32_t h0, l0, h1, l1;
    split2(v.x, v.y, h0, l0);
    split2(v.z, v.w, h1, l1);
    ((uint2*)hi)[i] = make_uint2(h0, h1);
    ((uint2*)lo)[i] = make_uint2(l0, l1);
}

// weight prep: w [3072, C, 3] fp32 -> hi/lo bf16 planes [3C][6144], k-major
__global__ void prep_w(const float* __restrict__ w,
                       __nv_bfloat16* __restrict__ wbhi,
                       __nv_bfloat16* __restrict__ wblo,
                       int C, int colbase)
{
    __shared__ float sm[32][97];
    const int tid = threadIdx.x;
    const int cb = blockIdx.x;
    const int jb = blockIdx.y;

    for (int i = tid; i < 32 * 96; i += 256) {
        int j = i / 96, q = i % 96;
        sm[j][q] = w[(size_t)(jb * 32 + j) * 3 * C + cb * 96 + q];
    }
    __syncthreads();

    for (int i = tid; i < 1536; i += 256) {
        int jp = i & 15;
        int tap = (i >> 4) % 3;
        int cl  = i / 48;
        int q   = cl * 3 + tap;
        uint32_t hp, lp;
        split2(sm[jp * 2][q], sm[jp * 2 + 1][q], hp, lp);
        size_t r = (size_t)tap * C + cb * 32 + cl;
        size_t off = r * NG + colbase + jb * 32 + jp * 2;
        *(uint32_t*)&wbhi[off] = hp;
        *(uint32_t*)&wblo[off] = lp;
    }
}

// ---------------------------------------------------------------------------
__device__ __forceinline__ void cp_async16(uint32_t smem, const void* gmem, int bytes)
{
    asm volatile("cp.async.cg.shared.global [%0], [%1], 16, %2;\n"
                 :: "r"(smem), "l"(gmem), "r"(bytes));
}
__device__ __forceinline__ void cp_commit()
{
    asm volatile("cp.async.commit_group;\n" ::: "memory");
}
template <int N>
__device__ __forceinline__ void cp_wait()
{
    asm volatile("cp.async.wait_group %0;\n" :: "n"(N) : "memory");
}

#define MMA_BF16(acc, a, b0, b1)                                              \
    asm volatile("mma.sync.aligned.m16n8k16.row.col.f32.bf16.bf16.f32 "       \
                 "{%0,%1,%2,%3}, {%4,%5,%6,%7}, {%8,%9}, {%0,%1,%2,%3};\n"    \
                 : "+f"(acc[0]), "+f"(acc[1]), "+f"(acc[2]), "+f"(acc[3])     \
                 : "r"(a[0]), "r"(a[1]), "r"(a[2]), "r"(a[3]),                \
                   "r"(b0), "r"(b1));

#define LDSM_X4(r, addr)                                                      \
    asm volatile("ldmatrix.sync.aligned.m8n8.x4.shared.b16 "                  \
                 "{%0,%1,%2,%3}, [%4];"                                       \
                 : "=r"((r)[0]), "=r"((r)[1]), "=r"((r)[2]), "=r"((r)[3])     \
                 : "r"(addr));

#define LDSM_X4T(r, addr)                                                     \
    asm volatile("ldmatrix.sync.aligned.m8n8.x4.trans.shared.b16 "            \
                 "{%0,%1,%2,%3}, [%4];"                                       \
                 : "=r"((r)[0]), "=r"((r)[1]), "=r"((r)[2]), "=r"((r)[3])     \
                 : "r"(addr));

// ---------------------------------------------------------------------------
// bf16x3 conv-as-GEMM with register-level software pipelining:
// BM=128 BN=64, 256 threads (4m x 2n warps, warp tile 32x32), 2 CTAs/SM.
// 4-stage cp.async ring: wait<1>+barrier guarantees stages kt AND kt+1
// arrived+visible -> next k16-step fragments are prefetched into the spare
// register buffer DURING the current 24-MMA burst (zero dependent stalls).
// XOR-swizzled smem (no padding): A chunk^(row&3), B chunk^(row&7).
// ---------------------------------------------------------------------------
// stage layout (bytes): Ahi 8192 | Alo 8192 | Bhi 4096 | Blo 4096 = 24576
#define STG_SZ   24576
#define STG_ALO  8192
#define STG_BHI  16384
#define STG_BLO  20480
#define SMEM_TOTAL (4 * STG_SZ)

template <int C>
__global__ void __launch_bounds__(256, 2) conv_gemm(
    const __nv_bfloat16* __restrict__ Ahi,
    const __nv_bfloat16* __restrict__ Alo,
    const __nv_bfloat16* __restrict__ Bhi_,
    const __nv_bfloat16* __restrict__ Blo_,
    const float* __restrict__ biasF,
    const float* __restrict__ biasR,
    float* __restrict__ gates)
{
    extern __shared__ char smraw[];

    const int tid  = threadIdx.x;          // 0..255
    const int lane = tid & 31;
    const int warp = tid >> 5;             // 0..7
    const int wm   = warp & 3;             // M
    const int wn   = warp >> 2;            // N (0..1)
    const int gp   = lane >> 2;
    const int tg   = lane & 3;
    const int lr   = lane & 15;
    const int lh   = lane >> 4;

    const int row0 = blockIdx.y << 7;
    const int col0 = blockIdx.x << 6;      // BN=64
    const int t0   = row0 & (Tlen - 1);
    const __nv_bfloat16* Ahb = Ahi + (size_t)(row0 - t0) * C;
    const __nv_bfloat16* Alb = Alo + (size_t)(row0 - t0) * C;

    float acc[2][4][4];
#pragma unroll
    for (int a = 0; a < 2; a++)
#pragma unroll
        for (int b = 0; b < 4; b++)
#pragma unroll
            for (int c = 0; c < 4; c++) acc[a][b][c] = 0.f;

    uint32_t sbase;
    asm("{ .reg .u64 t; cvta.to.shared.u64 t, %1; cvt.u32.u64 %0, t; }"
        : "=r"(sbase) : "l"(smraw));

    const int NKt = 3 * C / 32;

    // ---- stage loader: A 128x32 (hi/lo), B 32x64 (hi/lo), swizzled ----
    auto load_stage = [&](int kt, int st_idx) {
        const int kbase = kt << 5;
        const uint32_t st = sbase + st_idx * STG_SZ;
        const int tap   = kbase / C;
        const int cbase = kbase - tap * C;
        // A: 512 chunks/plane (128 rows x 4), 2 per thread per plane
#pragma unroll
        for (int r = 0; r < 2; r++) {
            int idx = tid + r * 256;
            int row = idx >> 2, c = idx & 3;
            int stt = t0 + row + tap - 1;
            int ok  = (stt >= 0) && (stt < Tlen);
            int stc = ok ? stt : 0;
            const __nv_bfloat16* srcH = Ahb + (size_t)stc * C + cbase + c * 8;
            const __nv_bfloat16* srcL = Alb + (size_t)stc * C + cbase + c * 8;
            uint32_t dst = st + (uint32_t)(row * 64 + (c ^ (row & 3)) * 16);
            cp_async16(dst,           srcH, ok ? 16 : 0);
            cp_async16(dst + STG_ALO, srcL, ok ? 16 : 0);
        }
        // B: 256 chunks/plane (32 rows x 8), 1 per thread per plane
        {
            int row = tid >> 3, c = tid & 7;
            size_t srcOff = (size_t)(kbase + row) * NG + col0 + c * 8;
            uint32_t dst = st + STG_BHI +
                           (uint32_t)(row * 128 + (c ^ (row & 7)) * 16);
            cp_async16(dst,                       Bhi_ + srcOff, 16);
            cp_async16(dst + (STG_BLO - STG_BHI), Blo_ + srcOff, 16);
        }
    };

    // ---- fragment buffers (double-buffered) ----
    uint32_t ahf[2][2][4], alf[2][2][4], bhf[2][8], blf[2][8];

    auto load_frags = [&](int buf, int st_idx, int ks) {
        const uint32_t st = sbase + st_idx * STG_SZ;
        // A: rows wm*32+lr (+16), chunk = ks*2+lh, phys = chunk ^ (lr&3)
        uint32_t aaddr = st + (uint32_t)((wm * 32 + lr) * 64 +
                                         ((ks * 2 + lh) ^ (lr & 3)) * 16);
        LDSM_X4(ahf[buf][0], aaddr);
        LDSM_X4(ahf[buf][1], aaddr + 1024);            // +16 rows * 64B
        LDSM_X4(alf[buf][0], aaddr + STG_ALO);
        LDSM_X4(alf[buf][1], aaddr + STG_ALO + 1024);
        // B: row = ks*16+lr, chunk = wn*4+np*2+lh, phys = chunk ^ (lr&7)
#pragma unroll
        for (int np = 0; np < 2; np++) {
            uint32_t baddr = st + STG_BHI +
                (uint32_t)((ks * 16 + lr) * 128 +
                           ((wn * 4 + np * 2 + lh) ^ (lr & 7)) * 16);
            LDSM_X4T(&bhf[buf][np * 4], baddr);
            LDSM_X4T(&blf[buf][np * 4], baddr + (STG_BLO - STG_BHI));
        }
    };

    auto mma_all = [&](int buf) {
        // term 1: lo*hi — 8 independent MMAs
#pragma unroll
        for (int ni = 0; ni < 4; ni++) {
            MMA_BF16(acc[0][ni], alf[buf][0], bhf[buf][ni * 2], bhf[buf][ni * 2 + 1]);
            MMA_BF16(acc[1][ni], alf[buf][1], bhf[buf][ni * 2], bhf[buf][ni * 2 + 1]);
        }
        // term 2: hi*lo
#pragma unroll
        for (int ni = 0; ni < 4; ni++) {
            MMA_BF16(acc[0][ni], ahf[buf][0], blf[buf][ni * 2], blf[buf][ni * 2 + 1]);
            MMA_BF16(acc[1][ni], ahf[buf][1], blf[buf][ni * 2], blf[buf][ni * 2 + 1]);
        }
        // term 3: hi*hi
#pragma unroll
        for (int ni = 0; ni < 4; ni++) {
            MMA_BF16(acc[0][ni], ahf[buf][0], bhf[buf][ni * 2], bhf[buf][ni * 2 + 1]);
            MMA_BF16(acc[1][ni], ahf[buf][1], bhf[buf][ni * 2], bhf[buf][ni * 2 + 1]);
        }
    };

    // ---- prologue: 3 stages in flight, stages 0,1 arrived+visible ----
    load_stage(0, 0); cp_commit();
    load_stage(1, 1); cp_commit();
    load_stage(2, 2); cp_commit();
    cp_wait<1>();          // groups 0,1 arrived (group 2 may pend)
    __syncthreads();       // stages 0,1 visible
    load_frags(0, 0, 0);   // preload (tile 0, ks=0)

    for (int kt = 0; kt < NKt; ++kt) {
        if (kt > 0) {
            cp_wait<1>();      // stages <= kt+1 arrived
            __syncthreads();   // visible; stage kt-1 fully consumed
        }
        if (kt + 3 < NKt) load_stage(kt + 3, (kt + 3) & 3);
        cp_commit();           // one group per iter (possibly empty)

        // ks=0: prefetch (kt, ks=1) into buf 1; compute buf 0
        load_frags(1, kt & 3, 1);
        mma_all(0);
        // ks=1: prefetch (kt+1, ks=0) into buf 0; compute buf 1
        if (kt + 1 < NKt) load_frags(0, (kt + 1) & 3, 0);
        mma_all(1);
    }

    // ---- epilogue: bias + activation (per-column act select) ----
    const int  dircol = (col0 >= 3072) ? 1 : 0;
    const float* bias = dircol ? biasR : biasF;
    const int  lcol0  = col0 - dircol * 3072;

#pragma unroll
    for (int mi = 0; mi < 2; mi++) {
        int r0g = row0 + wm * 32 + mi * 16 + gp;
#pragma unroll
        for (int ni = 0; ni < 4; ni++) {
            int cl  = lcol0 + wn * 32 + ni * 8 + tg * 2;   // bias/act index
            int cg  = col0  + wn * 32 + ni * 8 + tg * 2;   // global gate col
            const bool ztan = (cl >= 2048);                // z section -> tanh
            float b0v = bias[cl], b1v = bias[cl + 1];
            float v[4] = { acc[mi][ni][0] + b0v, acc[mi][ni][1] + b1v,
                           acc[mi][ni][2] + b0v, acc[mi][ni][3] + b1v };
#pragma unroll
            for (int j = 0; j < 4; j++) {
                if (ztan) v[j] = 1.f - __fdividef(2.f, __expf(2.f * v[j]) + 1.f);
                else      v[j] = __fdividef(1.f, 1.f + __expf(-v[j]));
            }
            *(float2*)(gates + (size_t)r0g * NG + cg)       = make_float2(v[0], v[1]);
            *(float2*)(gates + (size_t)(r0g + 8) * NG + cg) = make_float2(v[2], v[3]);
        }
    }
}

// ---------------------------------------------------------------------------
// fo-pool scan, both directions via blockIdx.y.
// ---------------------------------------------------------------------------
template <bool L0>
__global__ void scan2(const float* __restrict__ gates,
                      float* __restrict__ out_f32,
                      __nv_bfloat16* __restrict__ ohi,
                      __nv_bfloat16* __restrict__ olo,
                      float* __restrict__ hid,
                      float* __restrict__ cel)
{
    const int dir = blockIdx.y;
    const int gid = blockIdx.x * blockDim.x + threadIdx.x;
    const int b = gid >> 10, h = gid & 1023;
    const float* gb = gates + (size_t)b * Tlen * NG + dir * 3072 + h;
    const size_t obase = (size_t)b * Tlen * 2048 + dir * 1024 + h;
    float c = 0.f;

    auto emit = [&](int t, float hv) {
        size_t idx = obase + (size_t)t * 2048;
        if (L0) {
            __nv_bfloat16 hh = __float2bfloat16(hv);
            ohi[idx] = hh;
            olo[idx] = __float2bfloat16(hv - __bfloat162float(hh));
        } else {
            out_f32[idx] = hv;
        }
    };

    if (dir == 0) {
        float hl = 0.f;
        for (int tt = 0; tt < Tlen; tt += 8) {
            float fv[8], ov[8], zv[8];
#pragma unroll
            for (int i = 0; i < 8; i++) {
                size_t o_ = (size_t)(tt + i) * NG;
                fv[i] = gb[o_]; ov[i] = gb[o_ + 1024]; zv[i] = gb[o_ + 2048];
            }
#pragma unroll
            for (int i = 0; i < 8; i++) {
                c = fmaf(fv[i], c - zv[i], zv[i]);
                hl = c * ov[i];
                emit(tt + i, hl);
            }
        }
        hid[b * 2048 + h] = hl;
        cel[b * 2048 + h] = c;
    } else {
        float cfirst = 0.f, hfirst = 0.f;
        for (int tt = Tlen - 8; tt >= 0; tt -= 8) {
            float fv[8], ov[8], zv[8];
#pragma unroll
            for (int i = 0; i < 8; i++) {
                size_t o_ = (size_t)(tt + i) * NG;
                fv[i] = gb[o_]; ov[i] = gb[o_ + 1024]; zv[i] = gb[o_ + 2048];
            }
#pragma unroll
            for (int i = 7; i >= 0; i--) {
                c = fmaf(fv[i], c - zv[i], zv[i]);
                float hv = c * ov[i];
                emit(tt + i, hv);
                if (tt + i == Tlen - 1) { cfirst = c; hfirst = hv; }
            }
        }
        hid[1024 + b * 2048 + h] = hfirst;
        cel[1024 + b * 2048 + h] = cfirst;
    }
}

// ---------------------------------------------------------------------------
extern "C" void kernel_launch(void* const* d_in, const int* in_sizes, int n_in,
                              void* d_out, int out_size)
{
    const float* x   = (const float*)d_in[0];
    const float* w0f = (const float*)d_in[2];
    const float* b0f = (const float*)d_in[3];
    const float* w0r = (const float*)d_in[4];
    const float* b0r = (const float*)d_in[5];
    const float* w1f = (const float*)d_in[6];
    const float* b1f = (const float*)d_in[7];
    const float* w1r = (const float*)d_in[8];
    const float* b1r = (const float*)d_in[9];

    float* out1 = (float*)d_out;                         // [B,T,2H]
    float* hid  = out1 + (size_t)Bsz * Tlen * 2 * Hd;    // [4,B,H]
    float* cel  = hid + 4 * Bsz * Hd;

    float *gates; __nv_bfloat16 *xhi, *xlo, *o0hi, *o0lo, *wbhi, *wblo;
    cudaGetSymbolAddress((void**)&gates, g_gates);
    cudaGetSymbolAddress((void**)&xhi,  g_xhi);
    cudaGetSymbolAddress((void**)&xlo,  g_xlo);
    cudaGetSymbolAddress((void**)&o0hi, g_o0hi);
    cudaGetSymbolAddress((void**)&o0lo, g_o0lo);
    cudaGetSymbolAddress((void**)&wbhi, g_wbhi);
    cudaGetSymbolAddress((void**)&wblo, g_wblo);

    cudaFuncSetAttribute(conv_gemm<1024>,
                         cudaFuncAttributeMaxDynamicSharedMemorySize, SMEM_TOTAL);
    cudaFuncSetAttribute(conv_gemm<2048>,
                         cudaFuncAttributeMaxDynamicSharedMemorySize, SMEM_TOTAL);

    // ---- layer 0 ----
    prep_x<<<8192, 256>>>((const float4*)x, (uint32_t*)xhi, (uint32_t*)xlo);
    prep_w<<<dim3(32, 96), 256>>>(w0f, wbhi, wblo, 1024, 0);
    prep_w<<<dim3(32, 96), 256>>>(w0r, wbhi, wblo, 1024, 3072);
    conv_gemm<1024><<<dim3(96, 64), 256, SMEM_TOTAL>>>(xhi, xlo, wbhi, wblo,
                                                       b0f, b0r, gates);
    scan2<true><<<dim3(32, 2), 256>>>(gates, nullptr, o0hi, o0lo, hid, cel);
    // ---- layer 1 ----
    prep_w<<<dim3(64, 96), 256>>>(w1f, wbhi, wblo, 2048, 0);
    prep_w<<<dim3(64, 96), 256>>>(w1r, wbhi, wblo, 2048, 3072);
    conv_gemm<2048><<<dim3(96, 64), 256, SMEM_TOTAL>>>(o0hi, o0lo, wbhi, wblo,
                                                       b1f, b1r, gates);
    scan2<false><<<dim3(32, 2), 256>>>(gates, out1, nullptr, nullptr,
                                       hid + 16384, cel + 16384);
}